// round 1
// baseline (speedup 1.0000x reference)
#include <cuda_runtime.h>
#include <cstddef>

#define NU 150000
#define NB 75000
#define NE 1500000
#define DU 64
#define DB 128
#define HD 128

// ---------------- scratch (device globals; no allocation allowed) -----------
__device__ __align__(16) float g_u0[(size_t)NU * HD];
__device__ __align__(16) float g_u1[(size_t)NU * HD];
__device__ __align__(16) float g_b0[(size_t)NB * HD];
__device__ __align__(16) float g_b1[(size_t)NB * HD];
__device__ __align__(16) float g_sum_u[(size_t)NU * HD];
__device__ __align__(16) float g_sum_b[(size_t)NB * HD];
__device__ int   g_deg_u[NU];
__device__ int   g_deg_b[NB];
__device__ float g_inv_u[NU];
__device__ float g_inv_b[NB];

__device__ __forceinline__ float* upick(int i) { return i ? g_u1 : g_u0; }
__device__ __forceinline__ float* bpick(int i) { return i ? g_b1 : g_b0; }

// ---------------- init kernels ----------------------------------------------
__global__ void zero_deg_kernel() {
    int i = blockIdx.x * blockDim.x + threadIdx.x;
    if (i < NU) g_deg_u[i] = 0;
    else if (i < NU + NB) g_deg_b[i - NU] = 0;
}

__global__ void deg_kernel(const int* __restrict__ src, const int* __restrict__ dst) {
    int e = blockIdx.x * blockDim.x + threadIdx.x;
    if (e < NE) {
        atomicAdd(&g_deg_u[src[e]], 1);
        atomicAdd(&g_deg_b[dst[e]], 1);
    }
}

__global__ void inv_kernel() {
    int i = blockIdx.x * blockDim.x + threadIdx.x;
    if (i < NU)      g_inv_u[i]      = 1.0f / fmaxf((float)g_deg_u[i], 1.0f);
    else if (i < NU + NB) g_inv_b[i - NU] = 1.0f / fmaxf((float)g_deg_b[i - NU], 1.0f);
}

__global__ void zero_sums_kernel() {
    size_t i = (size_t)blockIdx.x * blockDim.x + threadIdx.x;
    float4 z = make_float4(0.f, 0.f, 0.f, 0.f);
    const size_t nu4 = (size_t)NU * (HD / 4);
    const size_t nb4 = (size_t)NB * (HD / 4);
    if (i < nu4)            ((float4*)g_sum_u)[i] = z;
    else if (i < nu4 + nb4) ((float4*)g_sum_b)[i - nu4] = z;
}

// ---------------- edge scatter (both directions, 1 warp per edge) -----------
__global__ void __launch_bounds__(256) scatter_kernel(
        const int* __restrict__ src, const int* __restrict__ dst, int cur) {
    const float* __restrict__ u = upick(cur);
    const float* __restrict__ b = bpick(cur);
    int gt   = blockIdx.x * blockDim.x + threadIdx.x;
    int e    = gt >> 5;
    int lane = threadIdx.x & 31;
    if (e >= NE) return;
    int s = src[e];
    int d = dst[e];

    float4 uv = *(const float4*)(u + (size_t)s * HD + lane * 4);
    float4 bv = *(const float4*)(b + (size_t)d * HD + lane * 4);

    float* sb = g_sum_b + (size_t)d * HD + lane * 4;
    float* su = g_sum_u + (size_t)s * HD + lane * 4;
    atomicAdd(sb + 0, uv.x); atomicAdd(sb + 1, uv.y);
    atomicAdd(sb + 2, uv.z); atomicAdd(sb + 3, uv.w);
    atomicAdd(su + 0, bv.x); atomicAdd(su + 1, bv.y);
    atomicAdd(su + 2, bv.z); atomicAdd(su + 3, bv.w);
}

// ---------------- projection GEMM: C[N,128] = A[N,K] @ W[K,128] + bias ------
// BM=64, BN=128, BK=16, 256 threads, 8x4 microtile.
__global__ void __launch_bounds__(256) proj_gemm(
        const float* __restrict__ A, int K,
        const float* __restrict__ W, const float* __restrict__ bias,
        int is_user) {
    __shared__ float As[16][64];
    __shared__ float Bs[16][128];

    float* __restrict__ C = is_user ? g_u0 : g_b0;
    const int N = is_user ? NU : NB;

    const int tid = threadIdx.x;
    const int tx = tid & 31;          // col group: 32 * 4 = 128
    const int ty = tid >> 5;          // row group: 8 * 8 = 64
    const int m_load = tid >> 2;      // 0..63
    const int k_load = (tid & 3) * 4; // 0,4,8,12
    const int row0 = blockIdx.x * 64;
    const int row_l = row0 + m_load;

    float acc[8][4];
#pragma unroll
    for (int i = 0; i < 8; i++)
#pragma unroll
        for (int j = 0; j < 4; j++) acc[i][j] = 0.f;

    for (int kt = 0; kt < K; kt += 16) {
        float4 av = make_float4(0.f, 0.f, 0.f, 0.f);
        if (row_l < N)
            av = *(const float4*)(A + (size_t)row_l * K + kt + k_load);
        As[k_load + 0][m_load] = av.x;
        As[k_load + 1][m_load] = av.y;
        As[k_load + 2][m_load] = av.z;
        As[k_load + 3][m_load] = av.w;
        {
            int f = tid * 4;
            *(float4*)&Bs[f >> 7][f & 127] =
                *(const float4*)(W + (size_t)(kt + (f >> 7)) * 128 + (f & 127));
            int f2 = f + 1024;
            *(float4*)&Bs[f2 >> 7][f2 & 127] =
                *(const float4*)(W + (size_t)(kt + (f2 >> 7)) * 128 + (f2 & 127));
        }
        __syncthreads();
#pragma unroll
        for (int k = 0; k < 16; k++) {
            float4 b0 = *(float4*)&Bs[k][tx * 4];
            float a0[8];
            *(float4*)&a0[0] = *(float4*)&As[k][ty * 8];
            *(float4*)&a0[4] = *(float4*)&As[k][ty * 8 + 4];
#pragma unroll
            for (int i = 0; i < 8; i++) {
                acc[i][0] += a0[i] * b0.x;
                acc[i][1] += a0[i] * b0.y;
                acc[i][2] += a0[i] * b0.z;
                acc[i][3] += a0[i] * b0.w;
            }
        }
        __syncthreads();
    }

    float4 bb = *(const float4*)(bias + tx * 4);
#pragma unroll
    for (int i = 0; i < 8; i++) {
        int row = row0 + ty * 8 + i;
        if (row < N) {
            float4 o;
            o.x = acc[i][0] + bb.x;
            o.y = acc[i][1] + bb.y;
            o.z = acc[i][2] + bb.z;
            o.w = acc[i][3] + bb.w;
            *(float4*)(C + (size_t)row * 128 + tx * 4) = o;
        }
    }
}

// ---------------- fused SAGE GEMM: out = relu([sum*inv | X] @ [Wl;Wr] + bl) --
// K = 256 virtual. BM=64, BN=128, BK=16.
__global__ void __launch_bounds__(256) sage_gemm(
        int is_user, int cur,
        const float* __restrict__ Wl, const float* __restrict__ Wr,
        const float* __restrict__ bias) {
    __shared__ float As[16][64];
    __shared__ float Bs[16][128];

    const float* __restrict__ sum = is_user ? g_sum_u : g_sum_b;
    const float* __restrict__ inv = is_user ? g_inv_u : g_inv_b;
    const float* __restrict__ X   = is_user ? upick(cur) : bpick(cur);
    float* __restrict__ out       = is_user ? upick(cur ^ 1) : bpick(cur ^ 1);
    const int N = is_user ? NU : NB;

    const int tid = threadIdx.x;
    const int tx = tid & 31;
    const int ty = tid >> 5;
    const int m_load = tid >> 2;
    const int k_load = (tid & 3) * 4;
    const int row0 = blockIdx.x * 64;
    const int row_l = row0 + m_load;

    float acc[8][4];
#pragma unroll
    for (int i = 0; i < 8; i++)
#pragma unroll
        for (int j = 0; j < 4; j++) acc[i][j] = 0.f;

    for (int kt = 0; kt < 256; kt += 16) {
        // A tile
        float4 av = make_float4(0.f, 0.f, 0.f, 0.f);
        if (row_l < N) {
            int kg = kt + k_load;
            if (kg < 128) {
                av = *(const float4*)(sum + (size_t)row_l * 128 + kg);
                float s = inv[row_l];
                av.x *= s; av.y *= s; av.z *= s; av.w *= s;
            } else {
                av = *(const float4*)(X + (size_t)row_l * 128 + (kg - 128));
            }
        }
        As[k_load + 0][m_load] = av.x;
        As[k_load + 1][m_load] = av.y;
        As[k_load + 2][m_load] = av.z;
        As[k_load + 3][m_load] = av.w;
        // B tile: rows kt..kt+15 of [Wl; Wr]
        {
            const float* Wsrc = (kt < 128) ? Wl : Wr;
            int kbase = (kt < 128) ? kt : kt - 128;
            int f = tid * 4;
            *(float4*)&Bs[f >> 7][f & 127] =
                *(const float4*)(Wsrc + (size_t)(kbase + (f >> 7)) * 128 + (f & 127));
            int f2 = f + 1024;
            *(float4*)&Bs[f2 >> 7][f2 & 127] =
                *(const float4*)(Wsrc + (size_t)(kbase + (f2 >> 7)) * 128 + (f2 & 127));
        }
        __syncthreads();
#pragma unroll
        for (int k = 0; k < 16; k++) {
            float4 b0 = *(float4*)&Bs[k][tx * 4];
            float a0[8];
            *(float4*)&a0[0] = *(float4*)&As[k][ty * 8];
            *(float4*)&a0[4] = *(float4*)&As[k][ty * 8 + 4];
#pragma unroll
            for (int i = 0; i < 8; i++) {
                acc[i][0] += a0[i] * b0.x;
                acc[i][1] += a0[i] * b0.y;
                acc[i][2] += a0[i] * b0.z;
                acc[i][3] += a0[i] * b0.w;
            }
        }
        __syncthreads();
    }

    float4 bb = *(const float4*)(bias + tx * 4);
#pragma unroll
    for (int i = 0; i < 8; i++) {
        int row = row0 + ty * 8 + i;
        if (row < N) {
            float4 o;
            o.x = fmaxf(acc[i][0] + bb.x, 0.f);
            o.y = fmaxf(acc[i][1] + bb.y, 0.f);
            o.z = fmaxf(acc[i][2] + bb.z, 0.f);
            o.w = fmaxf(acc[i][3] + bb.w, 0.f);
            *(float4*)(out + (size_t)row * 128 + tx * 4) = o;
        }
    }
}

// ---------------- layernorm (1 warp / row) ----------------------------------
__global__ void __launch_bounds__(256) ln_kernel(
        int is_user, int cur,
        const float* __restrict__ gamma, const float* __restrict__ beta,
        float* __restrict__ out) {
    const float* __restrict__ X = is_user ? upick(cur) : bpick(cur);
    const int N = is_user ? NU : NB;
    int w    = (blockIdx.x * blockDim.x + threadIdx.x) >> 5;
    int lane = threadIdx.x & 31;
    if (w >= N) return;

    float4 v = *(const float4*)(X + (size_t)w * 128 + lane * 4);
    float s = v.x + v.y + v.z + v.w;
#pragma unroll
    for (int o = 16; o; o >>= 1) s += __shfl_xor_sync(0xffffffffu, s, o);
    float mean = s * (1.0f / 128.0f);

    float dx = v.x - mean, dy = v.y - mean, dz = v.z - mean, dw = v.w - mean;
    float q = dx * dx + dy * dy + dz * dz + dw * dw;
#pragma unroll
    for (int o = 16; o; o >>= 1) q += __shfl_xor_sync(0xffffffffu, q, o);
    float rs = rsqrtf(q * (1.0f / 128.0f) + 1e-5f);

    float4 g  = *(const float4*)(gamma + lane * 4);
    float4 bt = *(const float4*)(beta + lane * 4);
    float4 o4;
    o4.x = dx * rs * g.x + bt.x;
    o4.y = dy * rs * g.y + bt.y;
    o4.z = dz * rs * g.z + bt.z;
    o4.w = dw * rs * g.w + bt.w;
    *(float4*)(out + (size_t)w * 128 + lane * 4) = o4;
}

// ---------------- launch ----------------------------------------------------
extern "C" void kernel_launch(void* const* d_in, const int* in_sizes, int n_in,
                              void* d_out, int out_size) {
    const float* user_x = (const float*)d_in[0];
    const float* book_x = (const float*)d_in[1];
    const int*   esrc   = (const int*)d_in[2];
    const int*   edst   = (const int*)d_in[3];
    const float* upw    = (const float*)d_in[4];
    const float* upb    = (const float*)d_in[5];
    const float* bpw    = (const float*)d_in[6];
    const float* bpb    = (const float*)d_in[7];
    const float* Wl     = (const float*)d_in[8];
    const float* bl     = (const float*)d_in[9];
    const float* Wr     = (const float*)d_in[10];
    const float* ug     = (const float*)d_in[11];
    const float* ube    = (const float*)d_in[12];
    const float* bg     = (const float*)d_in[13];
    const float* bbe    = (const float*)d_in[14];
    float* out = (float*)d_out;

    (void)in_sizes; (void)n_in; (void)out_size;

    // degrees / inverse counts (structure-only, but recomputed every call)
    zero_deg_kernel<<<(NU + NB + 255) / 256, 256>>>();
    deg_kernel<<<(NE + 255) / 256, 256>>>(esrc, edst);
    inv_kernel<<<(NU + NB + 255) / 256, 256>>>();

    // projections
    proj_gemm<<<(NU + 63) / 64, 256>>>(user_x, DU, upw, upb, 1);
    proj_gemm<<<(NB + 63) / 64, 256>>>(book_x, DB, bpw, bpb, 0);

    const size_t sum4 = ((size_t)(NU + NB) * (HD / 4) + 255) / 256;
    int cur = 0;
    for (int l = 0; l < 3; l++) {
        zero_sums_kernel<<<(unsigned)sum4, 256>>>();
        scatter_kernel<<<(NE * 32 + 255) / 256, 256>>>(esrc, edst, cur);
        sage_gemm<<<(NB + 63) / 64, 256>>>(0, cur, Wl + (size_t)l * 128 * 128,
                                           Wr + (size_t)l * 128 * 128, bl + (size_t)l * 128);
        sage_gemm<<<(NU + 63) / 64, 256>>>(1, cur, Wl + (size_t)l * 128 * 128,
                                           Wr + (size_t)l * 128 * 128, bl + (size_t)l * 128);
        cur ^= 1;
    }

    // layernorm -> output (u first, then b)
    ln_kernel<<<((size_t)NU * 32 + 255) / 256, 256>>>(1, cur, ug, ube, out);
    ln_kernel<<<((size_t)NB * 32 + 255) / 256, 256>>>(0, cur, bg, bbe,
                                                      out + (size_t)NU * HD);
}

// round 2
// speedup vs baseline: 2.2188x; 2.2188x over previous
#include <cuda_runtime.h>
#include <cstddef>

#define NU 150000
#define NB 75000
#define NE 1500000
#define DU 64
#define DB 128
#define HD 128

// ---------------- scratch (device globals; no allocation allowed) -----------
__device__ __align__(16) float g_u0[(size_t)NU * HD];
__device__ __align__(16) float g_u1[(size_t)NU * HD];
__device__ __align__(16) float g_b0[(size_t)NB * HD];
__device__ __align__(16) float g_b1[(size_t)NB * HD];
__device__ __align__(16) float g_sum_u[(size_t)NU * HD];   // holds MEAN after gather
__device__ __align__(16) float g_sum_b[(size_t)NB * HD];
__device__ int g_deg_u[NU];
__device__ int g_deg_b[NB];
__device__ int g_offs_u[NU + 1];
__device__ int g_offs_b[NB + 1];
__device__ int g_cur_u[NU];
__device__ int g_cur_b[NB];
__device__ int g_csr_u[NE];   // for each user, list of neighbor book ids
__device__ int g_csr_b[NE];   // for each book, list of neighbor user ids

__device__ __forceinline__ float* upick(int i) { return i ? g_u1 : g_u0; }
__device__ __forceinline__ float* bpick(int i) { return i ? g_b1 : g_b0; }

// ---------------- CSR build --------------------------------------------------
__global__ void zero_deg_kernel() {
    int i = blockIdx.x * blockDim.x + threadIdx.x;
    if (i < NU) g_deg_u[i] = 0;
    else if (i < NU + NB) g_deg_b[i - NU] = 0;
}

__global__ void deg_kernel(const int* __restrict__ src, const int* __restrict__ dst) {
    int e = blockIdx.x * blockDim.x + threadIdx.x;
    if (e < NE) {
        atomicAdd(&g_deg_u[src[e]], 1);
        atomicAdd(&g_deg_b[dst[e]], 1);
    }
}

// single-block exclusive scan: offs[0..n-1] = exclusive prefix, offs[n] = total
__global__ void __launch_bounds__(1024) scan_kernel(
        const int* __restrict__ deg, int* __restrict__ offs, int n) {
    __shared__ int wsum[32];
    __shared__ int s_carry;
    const int tid = threadIdx.x;
    if (tid == 0) s_carry = 0;
    __syncthreads();
    for (int base = 0; base < n; base += 1024) {
        int i = base + tid;
        int v = (i < n) ? deg[i] : 0;
        int x = v;
#pragma unroll
        for (int o = 1; o < 32; o <<= 1) {
            int y = __shfl_up_sync(0xffffffffu, x, o);
            if ((tid & 31) >= o) x += y;
        }
        if ((tid & 31) == 31) wsum[tid >> 5] = x;
        __syncthreads();
        if (tid < 32) {
            int w = wsum[tid];
#pragma unroll
            for (int o = 1; o < 32; o <<= 1) {
                int y = __shfl_up_sync(0xffffffffu, w, o);
                if (tid >= o) w += y;
            }
            wsum[tid] = w;   // inclusive scan of warp sums
        }
        __syncthreads();
        int warp_excl = (tid >= 32) ? wsum[(tid >> 5) - 1] : 0;
        int incl = x + warp_excl;
        if (i < n) offs[i] = s_carry + incl - v;
        __syncthreads();
        if (tid == 1023) s_carry += incl;   // incl of last thread == chunk total
        __syncthreads();
    }
    if (tid == 0) offs[n] = s_carry;
}

__global__ void copy_cursor_kernel() {
    int i = blockIdx.x * blockDim.x + threadIdx.x;
    if (i < NU) g_cur_u[i] = g_offs_u[i];
    else if (i < NU + NB) g_cur_b[i - NU] = g_offs_b[i - NU];
}

__global__ void fill_kernel(const int* __restrict__ src, const int* __restrict__ dst) {
    int e = blockIdx.x * blockDim.x + threadIdx.x;
    if (e < NE) {
        int s = src[e], d = dst[e];
        int pu = atomicAdd(&g_cur_u[s], 1);
        g_csr_u[pu] = d;
        int pb = atomicAdd(&g_cur_b[d], 1);
        g_csr_b[pb] = s;
    }
}

// ---------------- CSR gather: mean of neighbor rows (1 warp / dst) ----------
__global__ void __launch_bounds__(256) gather_mean(int is_user, int cur) {
    const float* __restrict__ src = is_user ? bpick(cur) : upick(cur);
    float* __restrict__ out       = is_user ? g_sum_u : g_sum_b;
    const int* __restrict__ offs  = is_user ? g_offs_u : g_offs_b;
    const int* __restrict__ idx   = is_user ? g_csr_u : g_csr_b;
    const int N = is_user ? NU : NB;

    int w    = (blockIdx.x * blockDim.x + threadIdx.x) >> 5;
    int lane = threadIdx.x & 31;
    if (w >= N) return;
    int s = offs[w], e = offs[w + 1];

    float ax = 0.f, ay = 0.f, az = 0.f, aw = 0.f;
    int j = s;
    for (; j + 4 <= e; j += 4) {
        int n0 = idx[j], n1 = idx[j + 1], n2 = idx[j + 2], n3 = idx[j + 3];
        float4 v0 = *(const float4*)(src + (size_t)n0 * HD + lane * 4);
        float4 v1 = *(const float4*)(src + (size_t)n1 * HD + lane * 4);
        float4 v2 = *(const float4*)(src + (size_t)n2 * HD + lane * 4);
        float4 v3 = *(const float4*)(src + (size_t)n3 * HD + lane * 4);
        ax += v0.x + v1.x + v2.x + v3.x;
        ay += v0.y + v1.y + v2.y + v3.y;
        az += v0.z + v1.z + v2.z + v3.z;
        aw += v0.w + v1.w + v2.w + v3.w;
    }
    for (; j < e; j++) {
        int n0 = idx[j];
        float4 v0 = *(const float4*)(src + (size_t)n0 * HD + lane * 4);
        ax += v0.x; ay += v0.y; az += v0.z; aw += v0.w;
    }
    float invd = 1.0f / fmaxf((float)(e - s), 1.0f);
    float4 o;
    o.x = ax * invd; o.y = ay * invd; o.z = az * invd; o.w = aw * invd;
    *(float4*)(out + (size_t)w * HD + lane * 4) = o;
}

// ---------------- projection GEMM: C[N,128] = A[N,K] @ W[K,128] + bias ------
__global__ void __launch_bounds__(256) proj_gemm(
        const float* __restrict__ A, int K,
        const float* __restrict__ W, const float* __restrict__ bias,
        int is_user) {
    __shared__ float As[16][64];
    __shared__ float Bs[16][128];

    float* __restrict__ C = is_user ? g_u0 : g_b0;
    const int N = is_user ? NU : NB;

    const int tid = threadIdx.x;
    const int tx = tid & 31;
    const int ty = tid >> 5;
    const int m_load = tid >> 2;
    const int k_load = (tid & 3) * 4;
    const int row0 = blockIdx.x * 64;
    const int row_l = row0 + m_load;

    float acc[8][4];
#pragma unroll
    for (int i = 0; i < 8; i++)
#pragma unroll
        for (int j = 0; j < 4; j++) acc[i][j] = 0.f;

    for (int kt = 0; kt < K; kt += 16) {
        float4 av = make_float4(0.f, 0.f, 0.f, 0.f);
        if (row_l < N)
            av = *(const float4*)(A + (size_t)row_l * K + kt + k_load);
        As[k_load + 0][m_load] = av.x;
        As[k_load + 1][m_load] = av.y;
        As[k_load + 2][m_load] = av.z;
        As[k_load + 3][m_load] = av.w;
        {
            int f = tid * 4;
            *(float4*)&Bs[f >> 7][f & 127] =
                *(const float4*)(W + (size_t)(kt + (f >> 7)) * 128 + (f & 127));
            int f2 = f + 1024;
            *(float4*)&Bs[f2 >> 7][f2 & 127] =
                *(const float4*)(W + (size_t)(kt + (f2 >> 7)) * 128 + (f2 & 127));
        }
        __syncthreads();
#pragma unroll
        for (int k = 0; k < 16; k++) {
            float4 b0 = *(float4*)&Bs[k][tx * 4];
            float a0[8];
            *(float4*)&a0[0] = *(float4*)&As[k][ty * 8];
            *(float4*)&a0[4] = *(float4*)&As[k][ty * 8 + 4];
#pragma unroll
            for (int i = 0; i < 8; i++) {
                acc[i][0] += a0[i] * b0.x;
                acc[i][1] += a0[i] * b0.y;
                acc[i][2] += a0[i] * b0.z;
                acc[i][3] += a0[i] * b0.w;
            }
        }
        __syncthreads();
    }

    float4 bb = *(const float4*)(bias + tx * 4);
#pragma unroll
    for (int i = 0; i < 8; i++) {
        int row = row0 + ty * 8 + i;
        if (row < N) {
            float4 o;
            o.x = acc[i][0] + bb.x;
            o.y = acc[i][1] + bb.y;
            o.z = acc[i][2] + bb.z;
            o.w = acc[i][3] + bb.w;
            *(float4*)(C + (size_t)row * 128 + tx * 4) = o;
        }
    }
}

// ---------------- fused SAGE GEMM: out = relu([mean | X] @ [Wl;Wr] + bl) ----
__global__ void __launch_bounds__(256) sage_gemm(
        int is_user, int cur,
        const float* __restrict__ Wl, const float* __restrict__ Wr,
        const float* __restrict__ bias) {
    __shared__ float As[16][64];
    __shared__ float Bs[16][128];

    const float* __restrict__ mean = is_user ? g_sum_u : g_sum_b;
    const float* __restrict__ X    = is_user ? upick(cur) : bpick(cur);
    float* __restrict__ out        = is_user ? upick(cur ^ 1) : bpick(cur ^ 1);
    const int N = is_user ? NU : NB;

    const int tid = threadIdx.x;
    const int tx = tid & 31;
    const int ty = tid >> 5;
    const int m_load = tid >> 2;
    const int k_load = (tid & 3) * 4;
    const int row0 = blockIdx.x * 64;
    const int row_l = row0 + m_load;

    float acc[8][4];
#pragma unroll
    for (int i = 0; i < 8; i++)
#pragma unroll
        for (int j = 0; j < 4; j++) acc[i][j] = 0.f;

    for (int kt = 0; kt < 256; kt += 16) {
        float4 av = make_float4(0.f, 0.f, 0.f, 0.f);
        if (row_l < N) {
            int kg = kt + k_load;
            if (kg < 128)
                av = *(const float4*)(mean + (size_t)row_l * 128 + kg);
            else
                av = *(const float4*)(X + (size_t)row_l * 128 + (kg - 128));
        }
        As[k_load + 0][m_load] = av.x;
        As[k_load + 1][m_load] = av.y;
        As[k_load + 2][m_load] = av.z;
        As[k_load + 3][m_load] = av.w;
        {
            const float* Wsrc = (kt < 128) ? Wl : Wr;
            int kbase = (kt < 128) ? kt : kt - 128;
            int f = tid * 4;
            *(float4*)&Bs[f >> 7][f & 127] =
                *(const float4*)(Wsrc + (size_t)(kbase + (f >> 7)) * 128 + (f & 127));
            int f2 = f + 1024;
            *(float4*)&Bs[f2 >> 7][f2 & 127] =
                *(const float4*)(Wsrc + (size_t)(kbase + (f2 >> 7)) * 128 + (f2 & 127));
        }
        __syncthreads();
#pragma unroll
        for (int k = 0; k < 16; k++) {
            float4 b0 = *(float4*)&Bs[k][tx * 4];
            float a0[8];
            *(float4*)&a0[0] = *(float4*)&As[k][ty * 8];
            *(float4*)&a0[4] = *(float4*)&As[k][ty * 8 + 4];
#pragma unroll
            for (int i = 0; i < 8; i++) {
                acc[i][0] += a0[i] * b0.x;
                acc[i][1] += a0[i] * b0.y;
                acc[i][2] += a0[i] * b0.z;
                acc[i][3] += a0[i] * b0.w;
            }
        }
        __syncthreads();
    }

    float4 bb = *(const float4*)(bias + tx * 4);
#pragma unroll
    for (int i = 0; i < 8; i++) {
        int row = row0 + ty * 8 + i;
        if (row < N) {
            float4 o;
            o.x = fmaxf(acc[i][0] + bb.x, 0.f);
            o.y = fmaxf(acc[i][1] + bb.y, 0.f);
            o.z = fmaxf(acc[i][2] + bb.z, 0.f);
            o.w = fmaxf(acc[i][3] + bb.w, 0.f);
            *(float4*)(out + (size_t)row * 128 + tx * 4) = o;
        }
    }
}

// ---------------- layernorm (1 warp / row) ----------------------------------
__global__ void __launch_bounds__(256) ln_kernel(
        int is_user, int cur,
        const float* __restrict__ gamma, const float* __restrict__ beta,
        float* __restrict__ out) {
    const float* __restrict__ X = is_user ? upick(cur) : bpick(cur);
    const int N = is_user ? NU : NB;
    int w    = (blockIdx.x * blockDim.x + threadIdx.x) >> 5;
    int lane = threadIdx.x & 31;
    if (w >= N) return;

    float4 v = *(const float4*)(X + (size_t)w * 128 + lane * 4);
    float s = v.x + v.y + v.z + v.w;
#pragma unroll
    for (int o = 16; o; o >>= 1) s += __shfl_xor_sync(0xffffffffu, s, o);
    float mean = s * (1.0f / 128.0f);

    float dx = v.x - mean, dy = v.y - mean, dz = v.z - mean, dw = v.w - mean;
    float q = dx * dx + dy * dy + dz * dz + dw * dw;
#pragma unroll
    for (int o = 16; o; o >>= 1) q += __shfl_xor_sync(0xffffffffu, q, o);
    float rs = rsqrtf(q * (1.0f / 128.0f) + 1e-5f);

    float4 g  = *(const float4*)(gamma + lane * 4);
    float4 bt = *(const float4*)(beta + lane * 4);
    float4 o4;
    o4.x = dx * rs * g.x + bt.x;
    o4.y = dy * rs * g.y + bt.y;
    o4.z = dz * rs * g.z + bt.z;
    o4.w = dw * rs * g.w + bt.w;
    *(float4*)(out + (size_t)w * 128 + lane * 4) = o4;
}

// ---------------- launch ----------------------------------------------------
extern "C" void kernel_launch(void* const* d_in, const int* in_sizes, int n_in,
                              void* d_out, int out_size) {
    const float* user_x = (const float*)d_in[0];
    const float* book_x = (const float*)d_in[1];
    const int*   esrc   = (const int*)d_in[2];
    const int*   edst   = (const int*)d_in[3];
    const float* upw    = (const float*)d_in[4];
    const float* upb    = (const float*)d_in[5];
    const float* bpw    = (const float*)d_in[6];
    const float* bpb    = (const float*)d_in[7];
    const float* Wl     = (const float*)d_in[8];
    const float* bl     = (const float*)d_in[9];
    const float* Wr     = (const float*)d_in[10];
    const float* ug     = (const float*)d_in[11];
    const float* ube    = (const float*)d_in[12];
    const float* bg     = (const float*)d_in[13];
    const float* bbe    = (const float*)d_in[14];
    float* out = (float*)d_out;

    (void)in_sizes; (void)n_in; (void)out_size;

    int* d_offs_u; cudaGetSymbolAddress((void**)&d_offs_u, g_offs_u);
    int* d_offs_b; cudaGetSymbolAddress((void**)&d_offs_b, g_offs_b);
    int* d_deg_u;  cudaGetSymbolAddress((void**)&d_deg_u,  g_deg_u);
    int* d_deg_b;  cudaGetSymbolAddress((void**)&d_deg_b,  g_deg_b);

    // ---- CSR build (once; reused by all 3 layers) ----
    zero_deg_kernel<<<(NU + NB + 255) / 256, 256>>>();
    deg_kernel<<<(NE + 255) / 256, 256>>>(esrc, edst);
    scan_kernel<<<1, 1024>>>(d_deg_u, d_offs_u, NU);
    scan_kernel<<<1, 1024>>>(d_deg_b, d_offs_b, NB);
    copy_cursor_kernel<<<(NU + NB + 255) / 256, 256>>>();
    fill_kernel<<<(NE + 255) / 256, 256>>>(esrc, edst);

    // ---- projections (overlap-friendly; independent of CSR) ----
    proj_gemm<<<(NU + 63) / 64, 256>>>(user_x, DU, upw, upb, 1);
    proj_gemm<<<(NB + 63) / 64, 256>>>(book_x, DB, bpw, bpb, 0);

    int cur = 0;
    for (int l = 0; l < 3; l++) {
        gather_mean<<<((size_t)NB * 32 + 255) / 256, 256>>>(0, cur);
        gather_mean<<<((size_t)NU * 32 + 255) / 256, 256>>>(1, cur);
        sage_gemm<<<(NB + 63) / 64, 256>>>(0, cur, Wl + (size_t)l * 128 * 128,
                                           Wr + (size_t)l * 128 * 128, bl + (size_t)l * 128);
        sage_gemm<<<(NU + 63) / 64, 256>>>(1, cur, Wl + (size_t)l * 128 * 128,
                                           Wr + (size_t)l * 128 * 128, bl + (size_t)l * 128);
        cur ^= 1;
    }

    ln_kernel<<<((size_t)NU * 32 + 255) / 256, 256>>>(1, cur, ug, ube, out);
    ln_kernel<<<((size_t)NB * 32 + 255) / 256, 256>>>(0, cur, bg, bbe,
                                                      out + (size_t)NU * HD);
}

// round 4
// speedup vs baseline: 3.6409x; 1.6409x over previous
#include <cuda_runtime.h>
#include <cuda_bf16.h>
#include <cstdint>
#include <cstddef>

#define NU 150000
#define NB 75000
#define NE 1500000
#define DU 64
#define DB 128
#define HD 128

#define NBLK_U 147   // ceil(150000/1024)
#define NBLK_B 74    // ceil(75000/1024)

// ---------------- scratch -----------------------------------------------------
__device__ __align__(16) float g_u0[(size_t)NU * HD];
__device__ __align__(16) float g_u1[(size_t)NU * HD];
__device__ __align__(16) float g_b0[(size_t)NB * HD];
__device__ __align__(16) float g_b1[(size_t)NB * HD];
__device__ __align__(16) float g_sum_u[(size_t)NU * HD];   // neighbor means
__device__ __align__(16) float g_sum_b[(size_t)NB * HD];
__device__ int g_deg_u[NU];
__device__ int g_deg_b[NB];
__device__ int g_offs_u[NU + 1];
__device__ int g_offs_b[NB + 1];
__device__ int g_bsum_u[NBLK_U + 1];
__device__ int g_bsum_b[NBLK_B + 1];
__device__ int g_cur_u[NU];
__device__ int g_cur_b[NB];
__device__ int g_csr_u[NE];
__device__ int g_csr_b[NE];

__device__ __forceinline__ float* upick(int i) { return i ? g_u1 : g_u0; }
__device__ __forceinline__ float* bpick(int i) { return i ? g_b1 : g_b0; }

// ---------------- CSR build ---------------------------------------------------
__global__ void zero_deg_kernel() {
    int i = blockIdx.x * blockDim.x + threadIdx.x;
    if (i < NU) g_deg_u[i] = 0;
    else if (i < NU + NB) g_deg_b[i - NU] = 0;
}

__global__ void deg_kernel(const int* __restrict__ src, const int* __restrict__ dst) {
    int e = blockIdx.x * blockDim.x + threadIdx.x;
    if (e < NE) {
        atomicAdd(&g_deg_u[src[e]], 1);
        atomicAdd(&g_deg_b[dst[e]], 1);
    }
}

__global__ void __launch_bounds__(1024) scan_blocks(
        const int* __restrict__ deg, int* __restrict__ offs,
        int* __restrict__ bsum, int n) {
    __shared__ int wsum[32];
    const int tid = threadIdx.x;
    int i = blockIdx.x * 1024 + tid;
    int v = (i < n) ? deg[i] : 0;
    int x = v;
#pragma unroll
    for (int o = 1; o < 32; o <<= 1) {
        int y = __shfl_up_sync(0xffffffffu, x, o);
        if ((tid & 31) >= o) x += y;
    }
    if ((tid & 31) == 31) wsum[tid >> 5] = x;
    __syncthreads();
    if (tid < 32) {
        int w = wsum[tid];
#pragma unroll
        for (int o = 1; o < 32; o <<= 1) {
            int y = __shfl_up_sync(0xffffffffu, w, o);
            if (tid >= o) w += y;
        }
        wsum[tid] = w;
    }
    __syncthreads();
    int we = (tid >= 32) ? wsum[(tid >> 5) - 1] : 0;
    int incl = x + we;
    if (i < n) offs[i] = incl - v;
    if (tid == 1023) bsum[blockIdx.x] = incl;
}

__global__ void __launch_bounds__(256) scan_small(int* __restrict__ a, int L) {
    __shared__ int wsum[8];
    const int tid = threadIdx.x;
    int v = (tid < L) ? a[tid] : 0;
    int x = v;
#pragma unroll
    for (int o = 1; o < 32; o <<= 1) {
        int y = __shfl_up_sync(0xffffffffu, x, o);
        if ((tid & 31) >= o) x += y;
    }
    if ((tid & 31) == 31) wsum[tid >> 5] = x;
    __syncthreads();
    if (tid == 0) {
        int c = 0;
#pragma unroll
        for (int w = 0; w < 8; w++) { int t = wsum[w]; wsum[w] = c; c += t; }
    }
    __syncthreads();
    int excl = x - v + wsum[tid >> 5];
    if (tid < L) a[tid] = excl;
    if (tid == L) a[L] = excl;
}

__global__ void scan_add(int* __restrict__ offs, const int* __restrict__ bsum,
                         int n, int nblk) {
    int i = blockIdx.x * blockDim.x + threadIdx.x;
    if (i < n) offs[i] += bsum[i >> 10];
    if (i == 0) offs[n] = bsum[nblk];
}

__global__ void copy_cursor_kernel() {
    int i = blockIdx.x * blockDim.x + threadIdx.x;
    if (i < NU) g_cur_u[i] = g_offs_u[i];
    else if (i < NU + NB) g_cur_b[i - NU] = g_offs_b[i - NU];
}

__global__ void fill_kernel(const int* __restrict__ src, const int* __restrict__ dst) {
    int e = blockIdx.x * blockDim.x + threadIdx.x;
    if (e < NE) {
        int s = src[e], d = dst[e];
        g_csr_u[atomicAdd(&g_cur_u[s], 1)] = d;
        g_csr_b[atomicAdd(&g_cur_b[d], 1)] = s;
    }
}

// ---------------- CSR gather: mean of neighbor rows (1 warp / dst) ------------
__global__ void __launch_bounds__(256) gather_mean(int is_user, int cur) {
    const float* __restrict__ src = is_user ? bpick(cur) : upick(cur);
    float* __restrict__ out       = is_user ? g_sum_u : g_sum_b;
    const int* __restrict__ offs  = is_user ? g_offs_u : g_offs_b;
    const int* __restrict__ idx   = is_user ? g_csr_u : g_csr_b;
    const int N = is_user ? NU : NB;

    int w    = (blockIdx.x * blockDim.x + threadIdx.x) >> 5;
    int lane = threadIdx.x & 31;
    if (w >= N) return;
    int s = offs[w], e = offs[w + 1];

    float ax = 0.f, ay = 0.f, az = 0.f, aw = 0.f;
    int j = s;
    for (; j + 4 <= e; j += 4) {
        int n0 = idx[j], n1 = idx[j + 1], n2 = idx[j + 2], n3 = idx[j + 3];
        float4 v0 = *(const float4*)(src + (size_t)n0 * HD + lane * 4);
        float4 v1 = *(const float4*)(src + (size_t)n1 * HD + lane * 4);
        float4 v2 = *(const float4*)(src + (size_t)n2 * HD + lane * 4);
        float4 v3 = *(const float4*)(src + (size_t)n3 * HD + lane * 4);
        ax += v0.x + v1.x + v2.x + v3.x;
        ay += v0.y + v1.y + v2.y + v3.y;
        az += v0.z + v1.z + v2.z + v3.z;
        aw += v0.w + v1.w + v2.w + v3.w;
    }
    for (; j < e; j++) {
        int n0 = idx[j];
        float4 v0 = *(const float4*)(src + (size_t)n0 * HD + lane * 4);
        ax += v0.x; ay += v0.y; az += v0.z; aw += v0.w;
    }
    float invd = 1.0f / fmaxf((float)(e - s), 1.0f);
    float4 o;
    o.x = ax * invd; o.y = ay * invd; o.z = az * invd; o.w = aw * invd;
    *(float4*)(out + (size_t)w * HD + lane * 4) = o;
}

// ---------------- projection GEMM (SIMT) ---------------------------------------
__global__ void __launch_bounds__(256) proj_gemm(
        const float* __restrict__ A, int K,
        const float* __restrict__ W, const float* __restrict__ bias,
        int is_user) {
    __shared__ float As[16][64];
    __shared__ float Bs[16][128];

    float* __restrict__ C = is_user ? g_u0 : g_b0;
    const int N = is_user ? NU : NB;

    const int tid = threadIdx.x;
    const int tx = tid & 31;
    const int ty = tid >> 5;
    const int m_load = tid >> 2;
    const int k_load = (tid & 3) * 4;
    const int row0 = blockIdx.x * 64;
    const int row_l = row0 + m_load;

    float acc[8][4];
#pragma unroll
    for (int i = 0; i < 8; i++)
#pragma unroll
        for (int j = 0; j < 4; j++) acc[i][j] = 0.f;

    for (int kt = 0; kt < K; kt += 16) {
        float4 av = make_float4(0.f, 0.f, 0.f, 0.f);
        if (row_l < N)
            av = *(const float4*)(A + (size_t)row_l * K + kt + k_load);
        As[k_load + 0][m_load] = av.x;
        As[k_load + 1][m_load] = av.y;
        As[k_load + 2][m_load] = av.z;
        As[k_load + 3][m_load] = av.w;
        {
            int f = tid * 4;
            *(float4*)&Bs[f >> 7][f & 127] =
                *(const float4*)(W + (size_t)(kt + (f >> 7)) * 128 + (f & 127));
            int f2 = f + 1024;
            *(float4*)&Bs[f2 >> 7][f2 & 127] =
                *(const float4*)(W + (size_t)(kt + (f2 >> 7)) * 128 + (f2 & 127));
        }
        __syncthreads();
#pragma unroll
        for (int k = 0; k < 16; k++) {
            float4 b0 = *(float4*)&Bs[k][tx * 4];
            float a0[8];
            *(float4*)&a0[0] = *(float4*)&As[k][ty * 8];
            *(float4*)&a0[4] = *(float4*)&As[k][ty * 8 + 4];
#pragma unroll
            for (int i = 0; i < 8; i++) {
                acc[i][0] += a0[i] * b0.x;
                acc[i][1] += a0[i] * b0.y;
                acc[i][2] += a0[i] * b0.z;
                acc[i][3] += a0[i] * b0.w;
            }
        }
        __syncthreads();
    }

    float4 bb = *(const float4*)(bias + tx * 4);
#pragma unroll
    for (int i = 0; i < 8; i++) {
        int row = row0 + ty * 8 + i;
        if (row < N) {
            float4 o;
            o.x = acc[i][0] + bb.x;
            o.y = acc[i][1] + bb.y;
            o.z = acc[i][2] + bb.z;
            o.w = acc[i][3] + bb.w;
            *(float4*)(C + (size_t)row * 128 + tx * 4) = o;
        }
    }
}

// ---------------- tensor-core SAGE GEMM via mma.sync (split-bf16) ---------------
// out[128, 128] = relu([mean|X](128,256) @ [Wl;Wr](256,128) + bias)
// D += Ahi*Bhi + Ahi*Blo + Alo*Bhi   (fp32 accum, err ~2^-16)
#define AST 72   // bf16 row stride in smem (conflict-free for fragment loads)
#define SMS_BIAS 0
#define SMS_AHI  1024
#define SMS_ALO  (SMS_AHI + 128 * AST * 2)
#define SMS_BHI  (SMS_ALO + 128 * AST * 2)
#define SMS_BLO  (SMS_BHI + 128 * AST * 2)
#define SMS_TOT  (SMS_BLO + 128 * AST * 2)

__device__ __forceinline__ void mma16816(float* d, const uint32_t* a,
                                         uint32_t b0, uint32_t b1) {
    asm volatile(
        "mma.sync.aligned.m16n8k16.row.col.f32.bf16.bf16.f32 "
        "{%0,%1,%2,%3}, {%4,%5,%6,%7}, {%8,%9}, {%0,%1,%2,%3};"
        : "+f"(d[0]), "+f"(d[1]), "+f"(d[2]), "+f"(d[3])
        : "r"(a[0]), "r"(a[1]), "r"(a[2]), "r"(a[3]), "r"(b0), "r"(b1));
}

__global__ void __launch_bounds__(256, 2) sage_mma(
        int is_user, int cur,
        const float* __restrict__ Wl, const float* __restrict__ Wr,
        const float* __restrict__ bias) {
    extern __shared__ char smem[];
    const int tid = threadIdx.x;
    const int wid = tid >> 5;
    const int lane = tid & 31;

    const float* __restrict__ mean = is_user ? g_sum_u : g_sum_b;
    const float* __restrict__ X    = is_user ? upick(cur) : bpick(cur);
    float* __restrict__ out        = is_user ? upick(cur ^ 1) : bpick(cur ^ 1);
    const int N = is_user ? NU : NB;
    const int row0 = blockIdx.x * 128;

    if (tid < 128) *(float*)(smem + SMS_BIAS + tid * 4) = bias[tid];

    const int warp_r = wid >> 1;     // 0..3 -> 32-row band
    const int warp_c = wid & 1;      // 0..1 -> 64-col band
    const int gid = lane >> 2;       // 0..7
    const int tig = lane & 3;        // 0..3

    float acc[2][8][4];
#pragma unroll
    for (int t = 0; t < 2; t++)
#pragma unroll
        for (int j = 0; j < 8; j++)
#pragma unroll
            for (int q = 0; q < 4; q++) acc[t][j][q] = 0.f;

    const int a_kq = (tid & 15) * 4;
    const int a_m0 = tid >> 4;
    const int bn = tid & 127;
    const int bk0 = (tid >> 7) * 32;

#pragma unroll 1
    for (int c = 0; c < 4; c++) {
        __syncthreads();   // protect smem reuse across chunks (and bias on c=0)

        // ---- stage A chunk (128 rows x 64 k), split hi/lo
        const int kg0 = c * 64;
        const float* __restrict__ asrc = (kg0 < 128) ? mean : X;
        const int akoff = (kg0 < 128) ? kg0 : kg0 - 128;
#pragma unroll
        for (int i = 0; i < 8; i++) {
            int m = a_m0 + i * 16;
            int gr = row0 + m;
            float4 v = make_float4(0.f, 0.f, 0.f, 0.f);
            if (gr < N) v = *(const float4*)(asrc + (size_t)gr * 128 + akoff + a_kq);
            __nv_bfloat162 h01 = __floats2bfloat162_rn(v.x, v.y);
            __nv_bfloat162 h23 = __floats2bfloat162_rn(v.z, v.w);
            float2 f01 = __bfloat1622float2(h01);
            float2 f23 = __bfloat1622float2(h23);
            __nv_bfloat162 l01 = __floats2bfloat162_rn(v.x - f01.x, v.y - f01.y);
            __nv_bfloat162 l23 = __floats2bfloat162_rn(v.z - f23.x, v.w - f23.y);
            uint32_t off = (uint32_t)(m * AST + a_kq) * 2;
            *(__nv_bfloat162*)(smem + SMS_AHI + off)     = h01;
            *(__nv_bfloat162*)(smem + SMS_AHI + off + 4) = h23;
            *(__nv_bfloat162*)(smem + SMS_ALO + off)     = l01;
            *(__nv_bfloat162*)(smem + SMS_ALO + off + 4) = l23;
        }

        // ---- stage B chunk: Bs[n][k] = W[kb+k][n], split hi/lo
        const float* __restrict__ wsrc = (kg0 < 128) ? Wl : Wr;
        const int kb = (kg0 < 128) ? kg0 : kg0 - 128;
#pragma unroll 8
        for (int j = 0; j < 32; j++) {
            int kk = bk0 + j;
            float w = wsrc[(size_t)(kb + kk) * 128 + bn];
            __nv_bfloat16 h = __float2bfloat16(w);
            __nv_bfloat16 l = __float2bfloat16(w - __bfloat162float(h));
            uint32_t off = (uint32_t)(bn * AST + kk) * 2;
            *(__nv_bfloat16*)(smem + SMS_BHI + off) = h;
            *(__nv_bfloat16*)(smem + SMS_BLO + off) = l;
        }
        __syncthreads();

        // ---- compute: 4 k16-steps
#pragma unroll
        for (int ks = 0; ks < 4; ks++) {
            const int k0 = ks * 16;
            uint32_t ah[8], al[8];
#pragma unroll
            for (int t = 0; t < 2; t++) {
                int r0 = warp_r * 32 + t * 16 + gid;
                uint32_t o0 = (uint32_t)(r0 * AST + k0 + tig * 2) * 2;
                uint32_t o1 = (uint32_t)((r0 + 8) * AST + k0 + tig * 2) * 2;
                ah[t * 4 + 0] = *(const uint32_t*)(smem + SMS_AHI + o0);
                ah[t * 4 + 1] = *(const uint32_t*)(smem + SMS_AHI + o1);
                ah[t * 4 + 2] = *(const uint32_t*)(smem + SMS_AHI + o0 + 16);
                ah[t * 4 + 3] = *(const uint32_t*)(smem + SMS_AHI + o1 + 16);
                al[t * 4 + 0] = *(const uint32_t*)(smem + SMS_ALO + o0);
                al[t * 4 + 1] = *(const uint32_t*)(smem + SMS_ALO + o1);
                al[t * 4 + 2] = *(const uint32_t*)(smem + SMS_ALO + o0 + 16);
                al[t * 4 + 3] = *(const uint32_t*)(smem + SMS_ALO + o1 + 16);
            }
#pragma unroll
            for (int j = 0; j < 8; j++) {
                int n = warp_c * 64 + j * 8 + gid;
                uint32_t ob = (uint32_t)(n * AST + k0 + tig * 2) * 2;
                uint32_t bh0 = *(const uint32_t*)(smem + SMS_BHI + ob);
                uint32_t bh1 = *(const uint32_t*)(smem + SMS_BHI + ob + 16);
                uint32_t bl0 = *(const uint32_t*)(smem + SMS_BLO + ob);
                uint32_t bl1 = *(const uint32_t*)(smem + SMS_BLO + ob + 16);
#pragma unroll
                for (int t = 0; t < 2; t++) {
                    mma16816(acc[t][j], ah + t * 4, bh0, bh1);
                    mma16816(acc[t][j], ah + t * 4, bl0, bl1);
                    mma16816(acc[t][j], al + t * 4, bh0, bh1);
                }
            }
        }
    }

    // ---- epilogue: bias + relu, fp32 stores
    const float* bias_s = (const float*)(smem + SMS_BIAS);
#pragma unroll
    for (int t = 0; t < 2; t++) {
        int r_lo = row0 + warp_r * 32 + t * 16 + gid;
        int r_hi = r_lo + 8;
#pragma unroll
        for (int j = 0; j < 8; j++) {
            int col = warp_c * 64 + j * 8 + tig * 2;
            float bx = bias_s[col], by = bias_s[col + 1];
            if (r_lo < N) {
                float2 o;
                o.x = fmaxf(acc[t][j][0] + bx, 0.f);
                o.y = fmaxf(acc[t][j][1] + by, 0.f);
                *(float2*)(out + (size_t)r_lo * 128 + col) = o;
            }
            if (r_hi < N) {
                float2 o;
                o.x = fmaxf(acc[t][j][2] + bx, 0.f);
                o.y = fmaxf(acc[t][j][3] + by, 0.f);
                *(float2*)(out + (size_t)r_hi * 128 + col) = o;
            }
        }
    }
}

// ---------------- layernorm (1 warp / row) -------------------------------------
__global__ void __launch_bounds__(256) ln_kernel(
        int is_user, int cur,
        const float* __restrict__ gamma, const float* __restrict__ beta,
        float* __restrict__ out) {
    const float* __restrict__ X = is_user ? upick(cur) : bpick(cur);
    const int N = is_user ? NU : NB;
    int w    = (blockIdx.x * blockDim.x + threadIdx.x) >> 5;
    int lane = threadIdx.x & 31;
    if (w >= N) return;

    float4 v = *(const float4*)(X + (size_t)w * 128 + lane * 4);
    float s = v.x + v.y + v.z + v.w;
#pragma unroll
    for (int o = 16; o; o >>= 1) s += __shfl_xor_sync(0xffffffffu, s, o);
    float mean = s * (1.0f / 128.0f);

    float dx = v.x - mean, dy = v.y - mean, dz = v.z - mean, dw = v.w - mean;
    float q = dx * dx + dy * dy + dz * dz + dw * dw;
#pragma unroll
    for (int o = 16; o; o >>= 1) q += __shfl_xor_sync(0xffffffffu, q, o);
    float rs = rsqrtf(q * (1.0f / 128.0f) + 1e-5f);

    float4 g  = *(const float4*)(gamma + lane * 4);
    float4 bt = *(const float4*)(beta + lane * 4);
    float4 o4;
    o4.x = dx * rs * g.x + bt.x;
    o4.y = dy * rs * g.y + bt.y;
    o4.z = dz * rs * g.z + bt.z;
    o4.w = dw * rs * g.w + bt.w;
    *(float4*)(out + (size_t)w * 128 + lane * 4) = o4;
}

// ---------------- launch --------------------------------------------------------
extern "C" void kernel_launch(void* const* d_in, const int* in_sizes, int n_in,
                              void* d_out, int out_size) {
    const float* user_x = (const float*)d_in[0];
    const float* book_x = (const float*)d_in[1];
    const int*   esrc   = (const int*)d_in[2];
    const int*   edst   = (const int*)d_in[3];
    const float* upw    = (const float*)d_in[4];
    const float* upb    = (const float*)d_in[5];
    const float* bpw    = (const float*)d_in[6];
    const float* bpb    = (const float*)d_in[7];
    const float* Wl     = (const float*)d_in[8];
    const float* bl     = (const float*)d_in[9];
    const float* Wr     = (const float*)d_in[10];
    const float* ug     = (const float*)d_in[11];
    const float* ube    = (const float*)d_in[12];
    const float* bg     = (const float*)d_in[13];
    const float* bbe    = (const float*)d_in[14];
    float* out = (float*)d_out;

    (void)in_sizes; (void)n_in; (void)out_size;

    cudaFuncSetAttribute(sage_mma, cudaFuncAttributeMaxDynamicSharedMemorySize, SMS_TOT);

    int* d_offs_u; cudaGetSymbolAddress((void**)&d_offs_u, g_offs_u);
    int* d_offs_b; cudaGetSymbolAddress((void**)&d_offs_b, g_offs_b);
    int* d_deg_u;  cudaGetSymbolAddress((void**)&d_deg_u,  g_deg_u);
    int* d_deg_b;  cudaGetSymbolAddress((void**)&d_deg_b,  g_deg_b);
    int* d_bsum_u; cudaGetSymbolAddress((void**)&d_bsum_u, g_bsum_u);
    int* d_bsum_b; cudaGetSymbolAddress((void**)&d_bsum_b, g_bsum_b);

    // ---- CSR build (once; reused by all 3 layers) ----
    zero_deg_kernel<<<(NU + NB + 255) / 256, 256>>>();
    deg_kernel<<<(NE + 255) / 256, 256>>>(esrc, edst);
    scan_blocks<<<NBLK_U, 1024>>>(d_deg_u, d_offs_u, d_bsum_u, NU);
    scan_blocks<<<NBLK_B, 1024>>>(d_deg_b, d_offs_b, d_bsum_b, NB);
    scan_small<<<1, 256>>>(d_bsum_u, NBLK_U);
    scan_small<<<1, 256>>>(d_bsum_b, NBLK_B);
    scan_add<<<(NU + 255) / 256, 256>>>(d_offs_u, d_bsum_u, NU, NBLK_U);
    scan_add<<<(NB + 255) / 256, 256>>>(d_offs_b, d_bsum_b, NB, NBLK_B);
    copy_cursor_kernel<<<(NU + NB + 255) / 256, 256>>>();
    fill_kernel<<<(NE + 255) / 256, 256>>>(esrc, edst);

    // ---- projections ----
    proj_gemm<<<(NU + 63) / 64, 256>>>(user_x, DU, upw, upb, 1);
    proj_gemm<<<(NB + 63) / 64, 256>>>(book_x, DB, bpw, bpb, 0);

    int cur = 0;
    for (int l = 0; l < 3; l++) {
        gather_mean<<<((size_t)NB * 32 + 255) / 256, 256>>>(0, cur);
        gather_mean<<<((size_t)NU * 32 + 255) / 256, 256>>>(1, cur);
        sage_mma<<<(NB + 127) / 128, 256, SMS_TOT>>>(0, cur, Wl + (size_t)l * 128 * 128,
                                                     Wr + (size_t)l * 128 * 128,
                                                     bl + (size_t)l * 128);
        sage_mma<<<(NU + 127) / 128, 256, SMS_TOT>>>(1, cur, Wl + (size_t)l * 128 * 128,
                                                     Wr + (size_t)l * 128 * 128,
                                                     bl + (size_t)l * 128);
        cur ^= 1;
    }

    ln_kernel<<<((size_t)NU * 32 + 255) / 256, 256>>>(1, cur, ug, ube, out);
    ln_kernel<<<((size_t)NB * 32 + 255) / 256, 256>>>(0, cur, bg, bbe,
                                                      out + (size_t)NU * HD);
}

// round 5
// speedup vs baseline: 4.0076x; 1.1007x over previous
#include <cuda_runtime.h>
#include <cuda_fp16.h>
#include <cstdint>
#include <cstddef>

#define NU 150000
#define NB 75000
#define NE 1500000
#define DU 64
#define DB 128
#define HD 128

#define NBLK_U 147   // ceil(150000/1024)
#define NBLK_B 74    // ceil(75000/1024)

// ---------------- scratch -----------------------------------------------------
// activations stored as fp16 hi + lo pairs (x = hi + lo, err ~2^-22)
__device__ __align__(16) __half g_uh0[(size_t)NU * HD];
__device__ __align__(16) __half g_ul0[(size_t)NU * HD];
__device__ __align__(16) __half g_uh1[(size_t)NU * HD];
__device__ __align__(16) __half g_ul1[(size_t)NU * HD];
__device__ __align__(16) __half g_bh0[(size_t)NB * HD];
__device__ __align__(16) __half g_bl0[(size_t)NB * HD];
__device__ __align__(16) __half g_bh1[(size_t)NB * HD];
__device__ __align__(16) __half g_bl1[(size_t)NB * HD];
__device__ __align__(16) float g_sum_u[(size_t)NU * HD];   // fp32 neighbor means
__device__ __align__(16) float g_sum_b[(size_t)NB * HD];
__device__ int g_deg_u[NU];
__device__ int g_deg_b[NB];
__device__ int g_offs_u[NU + 1];
__device__ int g_offs_b[NB + 1];
__device__ int g_bsum_u[NBLK_U + 1];
__device__ int g_bsum_b[NBLK_B + 1];
__device__ int g_cur_u[NU];
__device__ int g_cur_b[NB];
__device__ int g_csr_u[NE];
__device__ int g_csr_b[NE];

__device__ __forceinline__ __half* uh(int i) { return i ? g_uh1 : g_uh0; }
__device__ __forceinline__ __half* ul(int i) { return i ? g_ul1 : g_ul0; }
__device__ __forceinline__ __half* bh(int i) { return i ? g_bh1 : g_bh0; }
__device__ __forceinline__ __half* bl(int i) { return i ? g_bl1 : g_bl0; }

// ---------------- CSR build ---------------------------------------------------
__global__ void zero_deg_kernel() {
    int i = blockIdx.x * blockDim.x + threadIdx.x;
    if (i < NU) g_deg_u[i] = 0;
    else if (i < NU + NB) g_deg_b[i - NU] = 0;
}

__global__ void deg_kernel(const int* __restrict__ src, const int* __restrict__ dst) {
    int e = blockIdx.x * blockDim.x + threadIdx.x;
    if (e < NE) {
        atomicAdd(&g_deg_u[src[e]], 1);
        atomicAdd(&g_deg_b[dst[e]], 1);
    }
}

__global__ void __launch_bounds__(1024) scan_blocks(
        const int* __restrict__ deg, int* __restrict__ offs,
        int* __restrict__ bsum, int n) {
    __shared__ int wsum[32];
    const int tid = threadIdx.x;
    int i = blockIdx.x * 1024 + tid;
    int v = (i < n) ? deg[i] : 0;
    int x = v;
#pragma unroll
    for (int o = 1; o < 32; o <<= 1) {
        int y = __shfl_up_sync(0xffffffffu, x, o);
        if ((tid & 31) >= o) x += y;
    }
    if ((tid & 31) == 31) wsum[tid >> 5] = x;
    __syncthreads();
    if (tid < 32) {
        int w = wsum[tid];
#pragma unroll
        for (int o = 1; o < 32; o <<= 1) {
            int y = __shfl_up_sync(0xffffffffu, w, o);
            if (tid >= o) w += y;
        }
        wsum[tid] = w;
    }
    __syncthreads();
    int we = (tid >= 32) ? wsum[(tid >> 5) - 1] : 0;
    int incl = x + we;
    if (i < n) offs[i] = incl - v;
    if (tid == 1023) bsum[blockIdx.x] = incl;
}

__global__ void __launch_bounds__(256) scan_small(int* __restrict__ a, int L) {
    __shared__ int wsum[8];
    const int tid = threadIdx.x;
    int v = (tid < L) ? a[tid] : 0;
    int x = v;
#pragma unroll
    for (int o = 1; o < 32; o <<= 1) {
        int y = __shfl_up_sync(0xffffffffu, x, o);
        if ((tid & 31) >= o) x += y;
    }
    if ((tid & 31) == 31) wsum[tid >> 5] = x;
    __syncthreads();
    if (tid == 0) {
        int c = 0;
#pragma unroll
        for (int w = 0; w < 8; w++) { int t = wsum[w]; wsum[w] = c; c += t; }
    }
    __syncthreads();
    int excl = x - v + wsum[tid >> 5];
    if (tid < L) a[tid] = excl;
    if (tid == L) a[L] = excl;
}

__global__ void scan_add(int* __restrict__ offs, const int* __restrict__ bsum,
                         int n, int nblk) {
    int i = blockIdx.x * blockDim.x + threadIdx.x;
    if (i < n) offs[i] += bsum[i >> 10];
    if (i == 0) offs[n] = bsum[nblk];
}

__global__ void copy_cursor_kernel() {
    int i = blockIdx.x * blockDim.x + threadIdx.x;
    if (i < NU) g_cur_u[i] = g_offs_u[i];
    else if (i < NU + NB) g_cur_b[i - NU] = g_offs_b[i - NU];
}

__global__ void fill_kernel(const int* __restrict__ src, const int* __restrict__ dst) {
    int e = blockIdx.x * blockDim.x + threadIdx.x;
    if (e < NE) {
        int s = src[e], d = dst[e];
        g_csr_u[atomicAdd(&g_cur_u[s], 1)] = d;
        g_csr_b[atomicAdd(&g_cur_b[d], 1)] = s;
    }
}

// ---------------- CSR gather: mean of neighbor hi rows (1 warp / dst) ---------
// Reads fp16 hi only (256B/row); fp32 accumulate; fp32 mean out.
__global__ void __launch_bounds__(256) gather_mean(int is_user, int cur) {
    const __half* __restrict__ src = is_user ? bh(cur) : uh(cur);
    float* __restrict__ out        = is_user ? g_sum_u : g_sum_b;
    const int* __restrict__ offs   = is_user ? g_offs_u : g_offs_b;
    const int* __restrict__ idx    = is_user ? g_csr_u : g_csr_b;
    const int N = is_user ? NU : NB;

    int w    = (blockIdx.x * blockDim.x + threadIdx.x) >> 5;
    int lane = threadIdx.x & 31;
    if (w >= N) return;
    int s = offs[w], e = offs[w + 1];
    const int c4 = lane * 4;

    float ax = 0.f, ay = 0.f, az = 0.f, aw = 0.f;
    int j = s;
    for (; j + 4 <= e; j += 4) {
        int n0 = idx[j], n1 = idx[j + 1], n2 = idx[j + 2], n3 = idx[j + 3];
        uint2 r0 = *(const uint2*)(src + (size_t)n0 * HD + c4);
        uint2 r1 = *(const uint2*)(src + (size_t)n1 * HD + c4);
        uint2 r2 = *(const uint2*)(src + (size_t)n2 * HD + c4);
        uint2 r3 = *(const uint2*)(src + (size_t)n3 * HD + c4);
#pragma unroll
        for (int q = 0; q < 4; q++) {
            uint2 r = (q == 0) ? r0 : (q == 1) ? r1 : (q == 2) ? r2 : r3;
            float2 f0 = __half22float2(*(__half2*)&r.x);
            float2 f1 = __half22float2(*(__half2*)&r.y);
            ax += f0.x; ay += f0.y; az += f1.x; aw += f1.y;
        }
    }
    for (; j < e; j++) {
        uint2 r = *(const uint2*)(src + (size_t)idx[j] * HD + c4);
        float2 f0 = __half22float2(*(__half2*)&r.x);
        float2 f1 = __half22float2(*(__half2*)&r.y);
        ax += f0.x; ay += f0.y; az += f1.x; aw += f1.y;
    }
    float invd = 1.0f / fmaxf((float)(e - s), 1.0f);
    float4 o;
    o.x = ax * invd; o.y = ay * invd; o.z = az * invd; o.w = aw * invd;
    *(float4*)(out + (size_t)w * HD + c4) = o;
}

// ---------------- projection GEMM (SIMT, fp32 in, fp16 hi/lo out) -------------
__global__ void __launch_bounds__(256) proj_gemm(
        const float* __restrict__ A, int K,
        const float* __restrict__ W, const float* __restrict__ bias,
        int is_user) {
    __shared__ float As[16][64];
    __shared__ float Bs[16][128];

    __half* __restrict__ Ch = is_user ? g_uh0 : g_bh0;
    __half* __restrict__ Cl = is_user ? g_ul0 : g_bl0;
    const int N = is_user ? NU : NB;

    const int tid = threadIdx.x;
    const int tx = tid & 31;
    const int ty = tid >> 5;
    const int m_load = tid >> 2;
    const int k_load = (tid & 3) * 4;
    const int row0 = blockIdx.x * 64;
    const int row_l = row0 + m_load;

    float acc[8][4];
#pragma unroll
    for (int i = 0; i < 8; i++)
#pragma unroll
        for (int j = 0; j < 4; j++) acc[i][j] = 0.f;

    for (int kt = 0; kt < K; kt += 16) {
        float4 av = make_float4(0.f, 0.f, 0.f, 0.f);
        if (row_l < N)
            av = *(const float4*)(A + (size_t)row_l * K + kt + k_load);
        As[k_load + 0][m_load] = av.x;
        As[k_load + 1][m_load] = av.y;
        As[k_load + 2][m_load] = av.z;
        As[k_load + 3][m_load] = av.w;
        {
            int f = tid * 4;
            *(float4*)&Bs[f >> 7][f & 127] =
                *(const float4*)(W + (size_t)(kt + (f >> 7)) * 128 + (f & 127));
            int f2 = f + 1024;
            *(float4*)&Bs[f2 >> 7][f2 & 127] =
                *(const float4*)(W + (size_t)(kt + (f2 >> 7)) * 128 + (f2 & 127));
        }
        __syncthreads();
#pragma unroll
        for (int k = 0; k < 16; k++) {
            float4 b0 = *(float4*)&Bs[k][tx * 4];
            float a0[8];
            *(float4*)&a0[0] = *(float4*)&As[k][ty * 8];
            *(float4*)&a0[4] = *(float4*)&As[k][ty * 8 + 4];
#pragma unroll
            for (int i = 0; i < 8; i++) {
                acc[i][0] += a0[i] * b0.x;
                acc[i][1] += a0[i] * b0.y;
                acc[i][2] += a0[i] * b0.z;
                acc[i][3] += a0[i] * b0.w;
            }
        }
        __syncthreads();
    }

    float4 bb = *(const float4*)(bias + tx * 4);
#pragma unroll
    for (int i = 0; i < 8; i++) {
        int row = row0 + ty * 8 + i;
        if (row < N) {
            float ox = acc[i][0] + bb.x, oy = acc[i][1] + bb.y;
            float oz = acc[i][2] + bb.z, ow = acc[i][3] + bb.w;
            __half2 h01 = __float22half2_rn(make_float2(ox, oy));
            __half2 h23 = __float22half2_rn(make_float2(oz, ow));
            float2 f01 = __half22float2(h01);
            float2 f23 = __half22float2(h23);
            __half2 l01 = __float22half2_rn(make_float2(ox - f01.x, oy - f01.y));
            __half2 l23 = __float22half2_rn(make_float2(oz - f23.x, ow - f23.y));
            uint2 vh; vh.x = *(uint32_t*)&h01; vh.y = *(uint32_t*)&h23;
            uint2 vl; vl.x = *(uint32_t*)&l01; vl.y = *(uint32_t*)&l23;
            *(uint2*)(Ch + (size_t)row * 128 + tx * 4) = vh;
            *(uint2*)(Cl + (size_t)row * 128 + tx * 4) = vl;
        }
    }
}

// ---------------- tensor-core SAGE GEMM via mma.sync (split-fp16) ---------------
// out[128, 128] = relu([mean|X](128,256) @ [Wl;Wr](256,128) + bias)
// D += Ahi*Bhi + Ahi*Blo + Alo*Bhi   (fp32 accum)
#define AST 72   // fp16 row stride in smem (conflict-free for fragment loads)
#define SMS_BIAS 0
#define SMS_AHI  1024
#define SMS_ALO  (SMS_AHI + 128 * AST * 2)
#define SMS_BHI  (SMS_ALO + 128 * AST * 2)
#define SMS_BLO  (SMS_BHI + 128 * AST * 2)
#define SMS_TOT  (SMS_BLO + 128 * AST * 2)

__device__ __forceinline__ void mma16816(float* d, const uint32_t* a,
                                         uint32_t b0, uint32_t b1) {
    asm volatile(
        "mma.sync.aligned.m16n8k16.row.col.f32.f16.f16.f32 "
        "{%0,%1,%2,%3}, {%4,%5,%6,%7}, {%8,%9}, {%0,%1,%2,%3};"
        : "+f"(d[0]), "+f"(d[1]), "+f"(d[2]), "+f"(d[3])
        : "r"(a[0]), "r"(a[1]), "r"(a[2]), "r"(a[3]), "r"(b0), "r"(b1));
}

__global__ void __launch_bounds__(256, 2) sage_mma(
        int is_user, int cur,
        const float* __restrict__ Wl, const float* __restrict__ Wr,
        const float* __restrict__ bias) {
    extern __shared__ char smem[];
    const int tid = threadIdx.x;
    const int wid = tid >> 5;
    const int lane = tid & 31;

    const float* __restrict__ mean = is_user ? g_sum_u : g_sum_b;
    const __half* __restrict__ Xh  = is_user ? uh(cur) : bh(cur);
    const __half* __restrict__ Xl  = is_user ? ul(cur) : bl(cur);
    __half* __restrict__ Oh        = is_user ? uh(cur ^ 1) : bh(cur ^ 1);
    __half* __restrict__ Ol        = is_user ? ul(cur ^ 1) : bl(cur ^ 1);
    const int N = is_user ? NU : NB;
    const int row0 = blockIdx.x * 128;

    if (tid < 128) *(float*)(smem + SMS_BIAS + tid * 4) = bias[tid];

    const int warp_r = wid >> 1;
    const int warp_c = wid & 1;
    const int gid = lane >> 2;
    const int tig = lane & 3;

    float acc[2][8][4];
#pragma unroll
    for (int t = 0; t < 2; t++)
#pragma unroll
        for (int j = 0; j < 8; j++)
#pragma unroll
            for (int q = 0; q < 4; q++) acc[t][j][q] = 0.f;

    const int a_kq = (tid & 15) * 4;
    const int a_m0 = tid >> 4;
    const int bn = tid & 127;
    const int bk0 = (tid >> 7) * 32;

#pragma unroll 1
    for (int c = 0; c < 4; c++) {
        __syncthreads();

        const int kg0 = c * 64;
        if (kg0 < 128) {
            // mean chunk: fp32 -> fp16 hi/lo split
#pragma unroll
            for (int i = 0; i < 8; i++) {
                int m = a_m0 + i * 16;
                int gr = row0 + m;
                float4 v = make_float4(0.f, 0.f, 0.f, 0.f);
                if (gr < N) v = *(const float4*)(mean + (size_t)gr * 128 + kg0 + a_kq);
                __half2 h01 = __float22half2_rn(make_float2(v.x, v.y));
                __half2 h23 = __float22half2_rn(make_float2(v.z, v.w));
                float2 f01 = __half22float2(h01);
                float2 f23 = __half22float2(h23);
                __half2 l01 = __float22half2_rn(make_float2(v.x - f01.x, v.y - f01.y));
                __half2 l23 = __float22half2_rn(make_float2(v.z - f23.x, v.w - f23.y));
                uint32_t off = (uint32_t)(m * AST + a_kq) * 2;
                *(__half2*)(smem + SMS_AHI + off)     = h01;
                *(__half2*)(smem + SMS_AHI + off + 4) = h23;
                *(__half2*)(smem + SMS_ALO + off)     = l01;
                *(__half2*)(smem + SMS_ALO + off + 4) = l23;
            }
        } else {
            // X chunk: hi/lo already split in global -> straight copy
            const int akoff = kg0 - 128;
#pragma unroll
            for (int i = 0; i < 8; i++) {
                int m = a_m0 + i * 16;
                int gr = row0 + m;
                uint2 vh = make_uint2(0u, 0u), vl = make_uint2(0u, 0u);
                if (gr < N) {
                    vh = *(const uint2*)(Xh + (size_t)gr * 128 + akoff + a_kq);
                    vl = *(const uint2*)(Xl + (size_t)gr * 128 + akoff + a_kq);
                }
                uint32_t off = (uint32_t)(m * AST + a_kq) * 2;
                *(uint2*)(smem + SMS_AHI + off) = vh;
                *(uint2*)(smem + SMS_ALO + off) = vl;
            }
        }

        // ---- stage B chunk: Bs[n][k] = W[kb+k][n], split hi/lo
        const float* __restrict__ wsrc = (kg0 < 128) ? Wl : Wr;
        const int kb = (kg0 < 128) ? kg0 : kg0 - 128;
#pragma unroll 8
        for (int j = 0; j < 32; j++) {
            int kk = bk0 + j;
            float w = wsrc[(size_t)(kb + kk) * 128 + bn];
            __half h = __float2half_rn(w);
            __half l = __float2half_rn(w - __half2float(h));
            uint32_t off = (uint32_t)(bn * AST + kk) * 2;
            *(__half*)(smem + SMS_BHI + off) = h;
            *(__half*)(smem + SMS_BLO + off) = l;
        }
        __syncthreads();

        // ---- compute: 4 k16-steps
#pragma unroll
        for (int ks = 0; ks < 4; ks++) {
            const int k0 = ks * 16;
            uint32_t ahr[8], alr[8];
#pragma unroll
            for (int t = 0; t < 2; t++) {
                int r0 = warp_r * 32 + t * 16 + gid;
                uint32_t o0 = (uint32_t)(r0 * AST + k0 + tig * 2) * 2;
                uint32_t o1 = (uint32_t)((r0 + 8) * AST + k0 + tig * 2) * 2;
                ahr[t * 4 + 0] = *(const uint32_t*)(smem + SMS_AHI + o0);
                ahr[t * 4 + 1] = *(const uint32_t*)(smem + SMS_AHI + o1);
                ahr[t * 4 + 2] = *(const uint32_t*)(smem + SMS_AHI + o0 + 16);
                ahr[t * 4 + 3] = *(const uint32_t*)(smem + SMS_AHI + o1 + 16);
                alr[t * 4 + 0] = *(const uint32_t*)(smem + SMS_ALO + o0);
                alr[t * 4 + 1] = *(const uint32_t*)(smem + SMS_ALO + o1);
                alr[t * 4 + 2] = *(const uint32_t*)(smem + SMS_ALO + o0 + 16);
                alr[t * 4 + 3] = *(const uint32_t*)(smem + SMS_ALO + o1 + 16);
            }
#pragma unroll
            for (int j = 0; j < 8; j++) {
                int n = warp_c * 64 + j * 8 + gid;
                uint32_t ob = (uint32_t)(n * AST + k0 + tig * 2) * 2;
                uint32_t bh0 = *(const uint32_t*)(smem + SMS_BHI + ob);
                uint32_t bh1 = *(const uint32_t*)(smem + SMS_BHI + ob + 16);
                uint32_t bl0 = *(const uint32_t*)(smem + SMS_BLO + ob);
                uint32_t bl1 = *(const uint32_t*)(smem + SMS_BLO + ob + 16);
#pragma unroll
                for (int t = 0; t < 2; t++) {
                    mma16816(acc[t][j], ahr + t * 4, bh0, bh1);
                    mma16816(acc[t][j], ahr + t * 4, bl0, bl1);
                    mma16816(acc[t][j], alr + t * 4, bh0, bh1);
                }
            }
        }
    }

    // ---- epilogue: bias + relu, fp16 hi/lo stores
    const float* bias_s = (const float*)(smem + SMS_BIAS);
#pragma unroll
    for (int t = 0; t < 2; t++) {
        int r_lo = row0 + warp_r * 32 + t * 16 + gid;
        int r_hi = r_lo + 8;
#pragma unroll
        for (int j = 0; j < 8; j++) {
            int col = warp_c * 64 + j * 8 + tig * 2;
            float bx = bias_s[col], by = bias_s[col + 1];
            if (r_lo < N) {
                float ox = fmaxf(acc[t][j][0] + bx, 0.f);
                float oy = fmaxf(acc[t][j][1] + by, 0.f);
                __half2 h = __float22half2_rn(make_float2(ox, oy));
                float2 f = __half22float2(h);
                __half2 l = __float22half2_rn(make_float2(ox - f.x, oy - f.y));
                *(__half2*)(Oh + (size_t)r_lo * 128 + col) = h;
                *(__half2*)(Ol + (size_t)r_lo * 128 + col) = l;
            }
            if (r_hi < N) {
                float ox = fmaxf(acc[t][j][2] + bx, 0.f);
                float oy = fmaxf(acc[t][j][3] + by, 0.f);
                __half2 h = __float22half2_rn(make_float2(ox, oy));
                float2 f = __half22float2(h);
                __half2 l = __float22half2_rn(make_float2(ox - f.x, oy - f.y));
                *(__half2*)(Oh + (size_t)r_hi * 128 + col) = h;
                *(__half2*)(Ol + (size_t)r_hi * 128 + col) = l;
            }
        }
    }
}

// ---------------- layernorm (1 warp / row, reads hi+lo) -----------------------
__global__ void __launch_bounds__(256) ln_kernel(
        int is_user, int cur,
        const float* __restrict__ gamma, const float* __restrict__ beta,
        float* __restrict__ out) {
    const __half* __restrict__ Xh = is_user ? uh(cur) : bh(cur);
    const __half* __restrict__ Xl = is_user ? ul(cur) : bl(cur);
    const int N = is_user ? NU : NB;
    int w    = (blockIdx.x * blockDim.x + threadIdx.x) >> 5;
    int lane = threadIdx.x & 31;
    if (w >= N) return;

    uint2 vh = *(const uint2*)(Xh + (size_t)w * 128 + lane * 4);
    uint2 vl = *(const uint2*)(Xl + (size_t)w * 128 + lane * 4);
    float2 h0 = __half22float2(*(__half2*)&vh.x);
    float2 h1 = __half22float2(*(__half2*)&vh.y);
    float2 l0 = __half22float2(*(__half2*)&vl.x);
    float2 l1 = __half22float2(*(__half2*)&vl.y);
    float4 v;
    v.x = h0.x + l0.x; v.y = h0.y + l0.y;
    v.z = h1.x + l1.x; v.w = h1.y + l1.y;

    float s = v.x + v.y + v.z + v.w;
#pragma unroll
    for (int o = 16; o; o >>= 1) s += __shfl_xor_sync(0xffffffffu, s, o);
    float mean = s * (1.0f / 128.0f);

    float dx = v.x - mean, dy = v.y - mean, dz = v.z - mean, dw = v.w - mean;
    float q = dx * dx + dy * dy + dz * dz + dw * dw;
#pragma unroll
    for (int o = 16; o; o >>= 1) q += __shfl_xor_sync(0xffffffffu, q, o);
    float rs = rsqrtf(q * (1.0f / 128.0f) + 1e-5f);

    float4 g  = *(const float4*)(gamma + lane * 4);
    float4 bt = *(const float4*)(beta + lane * 4);
    float4 o4;
    o4.x = dx * rs * g.x + bt.x;
    o4.y = dy * rs * g.y + bt.y;
    o4.z = dz * rs * g.z + bt.z;
    o4.w = dw * rs * g.w + bt.w;
    *(float4*)(out + (size_t)w * 128 + lane * 4) = o4;
}

// ---------------- launch --------------------------------------------------------
extern "C" void kernel_launch(void* const* d_in, const int* in_sizes, int n_in,
                              void* d_out, int out_size) {
    const float* user_x = (const float*)d_in[0];
    const float* book_x = (const float*)d_in[1];
    const int*   esrc   = (const int*)d_in[2];
    const int*   edst   = (const int*)d_in[3];
    const float* upw    = (const float*)d_in[4];
    const float* upb    = (const float*)d_in[5];
    const float* bpw    = (const float*)d_in[6];
    const float* bpb    = (const float*)d_in[7];
    const float* Wl     = (const float*)d_in[8];
    const float* bl_    = (const float*)d_in[9];
    const float* Wr     = (const float*)d_in[10];
    const float* ug     = (const float*)d_in[11];
    const float* ube    = (const float*)d_in[12];
    const float* bg     = (const float*)d_in[13];
    const float* bbe    = (const float*)d_in[14];
    float* out = (float*)d_out;

    (void)in_sizes; (void)n_in; (void)out_size;

    cudaFuncSetAttribute(sage_mma, cudaFuncAttributeMaxDynamicSharedMemorySize, SMS_TOT);

    int* d_offs_u; cudaGetSymbolAddress((void**)&d_offs_u, g_offs_u);
    int* d_offs_b; cudaGetSymbolAddress((void**)&d_offs_b, g_offs_b);
    int* d_deg_u;  cudaGetSymbolAddress((void**)&d_deg_u,  g_deg_u);
    int* d_deg_b;  cudaGetSymbolAddress((void**)&d_deg_b,  g_deg_b);
    int* d_bsum_u; cudaGetSymbolAddress((void**)&d_bsum_u, g_bsum_u);
    int* d_bsum_b; cudaGetSymbolAddress((void**)&d_bsum_b, g_bsum_b);

    // ---- CSR build (once; reused by all 3 layers) ----
    zero_deg_kernel<<<(NU + NB + 255) / 256, 256>>>();
    deg_kernel<<<(NE + 255) / 256, 256>>>(esrc, edst);
    scan_blocks<<<NBLK_U, 1024>>>(d_deg_u, d_offs_u, d_bsum_u, NU);
    scan_blocks<<<NBLK_B, 1024>>>(d_deg_b, d_offs_b, d_bsum_b, NB);
    scan_small<<<1, 256>>>(d_bsum_u, NBLK_U);
    scan_small<<<1, 256>>>(d_bsum_b, NBLK_B);
    scan_add<<<(NU + 255) / 256, 256>>>(d_offs_u, d_bsum_u, NU, NBLK_U);
    scan_add<<<(NB + 255) / 256, 256>>>(d_offs_b, d_bsum_b, NB, NBLK_B);
    copy_cursor_kernel<<<(NU + NB + 255) / 256, 256>>>();
    fill_kernel<<<(NE + 255) / 256, 256>>>(esrc, edst);

    // ---- projections ----
    proj_gemm<<<(NU + 63) / 64, 256>>>(user_x, DU, upw, upb, 1);
    proj_gemm<<<(NB + 63) / 64, 256>>>(book_x, DB, bpw, bpb, 0);

    int cur = 0;
    for (int l = 0; l < 3; l++) {
        gather_mean<<<((size_t)NB * 32 + 255) / 256, 256>>>(0, cur);
        gather_mean<<<((size_t)NU * 32 + 255) / 256, 256>>>(1, cur);
        sage_mma<<<(NB + 127) / 128, 256, SMS_TOT>>>(0, cur, Wl + (size_t)l * 128 * 128,
                                                     Wr + (size_t)l * 128 * 128,
                                                     bl_ + (size_t)l * 128);
        sage_mma<<<(NU + 127) / 128, 256, SMS_TOT>>>(1, cur, Wl + (size_t)l * 128 * 128,
                                                     Wr + (size_t)l * 128 * 128,
                                                     bl_ + (size_t)l * 128);
        cur ^= 1;
    }

    ln_kernel<<<((size_t)NU * 32 + 255) / 256, 256>>>(1, cur, ug, ube, out);
    ln_kernel<<<((size_t)NB * 32 + 255) / 256, 256>>>(0, cur, bg, bbe,
                                                      out + (size_t)NU * HD);
}

// round 6
// speedup vs baseline: 4.1776x; 1.0424x over previous
#include <cuda_runtime.h>
#include <cuda_fp16.h>
#include <cstdint>
#include <cstddef>

#define NU 150000
#define NB 75000
#define NE 1500000
#define DU 64
#define DB 128
#define HD 128

#define NBLK_U 147   // ceil(150000/1024)
#define NBLK_B 74    // ceil(75000/1024)
#define TB 586       // ceil(NB/128) sage tiles
#define TU 1172      // ceil(NU/128)

// ---------------- scratch -----------------------------------------------------
// activations stored as fp16 hi + lo pairs (x = hi + lo, err ~2^-22)
__device__ __align__(16) __half g_uh0[(size_t)NU * HD];
__device__ __align__(16) __half g_ul0[(size_t)NU * HD];
__device__ __align__(16) __half g_uh1[(size_t)NU * HD];
__device__ __align__(16) __half g_ul1[(size_t)NU * HD];
__device__ __align__(16) __half g_bh0[(size_t)NB * HD];
__device__ __align__(16) __half g_bl0[(size_t)NB * HD];
__device__ __align__(16) __half g_bh1[(size_t)NB * HD];
__device__ __align__(16) __half g_bl1[(size_t)NB * HD];
__device__ __align__(16) __half g_mh_u[(size_t)NU * HD];   // fp16 neighbor means (hi only)
__device__ __align__(16) __half g_mh_b[(size_t)NB * HD];
__device__ int g_deg_u[NU];
__device__ int g_deg_b[NB];
__device__ int g_offs_u[NU + 1];
__device__ int g_offs_b[NB + 1];
__device__ int g_bsum_u[NBLK_U + 1];
__device__ int g_bsum_b[NBLK_B + 1];
__device__ int g_cur_u[NU];
__device__ int g_cur_b[NB];
__device__ int g_csr_u[NE];
__device__ int g_csr_b[NE];

__device__ __forceinline__ __half* uh(int i) { return i ? g_uh1 : g_uh0; }
__device__ __forceinline__ __half* ul(int i) { return i ? g_ul1 : g_ul0; }
__device__ __forceinline__ __half* bh(int i) { return i ? g_bh1 : g_bh0; }
__device__ __forceinline__ __half* bl(int i) { return i ? g_bl1 : g_bl0; }

// ---------------- CSR build ---------------------------------------------------
__global__ void zero_deg_kernel() {
    int i = blockIdx.x * blockDim.x + threadIdx.x;
    if (i < NU) g_deg_u[i] = 0;
    else if (i < NU + NB) g_deg_b[i - NU] = 0;
}

__global__ void deg_kernel(const int* __restrict__ src, const int* __restrict__ dst) {
    int e = blockIdx.x * blockDim.x + threadIdx.x;
    if (e < NE) {
        atomicAdd(&g_deg_u[src[e]], 1);
        atomicAdd(&g_deg_b[dst[e]], 1);
    }
}

__global__ void __launch_bounds__(1024) scan_blocks(
        const int* __restrict__ deg, int* __restrict__ offs,
        int* __restrict__ bsum, int n) {
    __shared__ int wsum[32];
    const int tid = threadIdx.x;
    int i = blockIdx.x * 1024 + tid;
    int v = (i < n) ? deg[i] : 0;
    int x = v;
#pragma unroll
    for (int o = 1; o < 32; o <<= 1) {
        int y = __shfl_up_sync(0xffffffffu, x, o);
        if ((tid & 31) >= o) x += y;
    }
    if ((tid & 31) == 31) wsum[tid >> 5] = x;
    __syncthreads();
    if (tid < 32) {
        int w = wsum[tid];
#pragma unroll
        for (int o = 1; o < 32; o <<= 1) {
            int y = __shfl_up_sync(0xffffffffu, w, o);
            if (tid >= o) w += y;
        }
        wsum[tid] = w;
    }
    __syncthreads();
    int we = (tid >= 32) ? wsum[(tid >> 5) - 1] : 0;
    int incl = x + we;
    if (i < n) offs[i] = incl - v;
    if (tid == 1023) bsum[blockIdx.x] = incl;
}

__global__ void __launch_bounds__(256) scan_small(int* __restrict__ a, int L) {
    __shared__ int wsum[8];
    const int tid = threadIdx.x;
    int v = (tid < L) ? a[tid] : 0;
    int x = v;
#pragma unroll
    for (int o = 1; o < 32; o <<= 1) {
        int y = __shfl_up_sync(0xffffffffu, x, o);
        if ((tid & 31) >= o) x += y;
    }
    if ((tid & 31) == 31) wsum[tid >> 5] = x;
    __syncthreads();
    if (tid == 0) {
        int c = 0;
#pragma unroll
        for (int w = 0; w < 8; w++) { int t = wsum[w]; wsum[w] = c; c += t; }
    }
    __syncthreads();
    int excl = x - v + wsum[tid >> 5];
    if (tid < L) a[tid] = excl;
    if (tid == L) a[L] = excl;
}

__global__ void scan_add(int* __restrict__ offs, const int* __restrict__ bsum,
                         int n, int nblk) {
    int i = blockIdx.x * blockDim.x + threadIdx.x;
    if (i < n) offs[i] += bsum[i >> 10];
    if (i == 0) offs[n] = bsum[nblk];
}

__global__ void copy_cursor_kernel() {
    int i = blockIdx.x * blockDim.x + threadIdx.x;
    if (i < NU) g_cur_u[i] = g_offs_u[i];
    else if (i < NU + NB) g_cur_b[i - NU] = g_offs_b[i - NU];
}

__global__ void fill_kernel(const int* __restrict__ src, const int* __restrict__ dst) {
    int e = blockIdx.x * blockDim.x + threadIdx.x;
    if (e < NE) {
        int s = src[e], d = dst[e];
        g_csr_u[atomicAdd(&g_cur_u[s], 1)] = d;
        g_csr_b[atomicAdd(&g_cur_b[d], 1)] = s;
    }
}

// ---------------- CSR gather (both directions, 1 warp / dst row) --------------
// Reads fp16 hi rows; fp32 accumulate; fp16 hi mean out.
__global__ void __launch_bounds__(256) gather_mean(int cur) {
    int gw   = (blockIdx.x * blockDim.x + threadIdx.x) >> 5;
    int lane = threadIdx.x & 31;

    int is_user, w;
    if (gw < NB) { is_user = 0; w = gw; }
    else         { is_user = 1; w = gw - NB; if (w >= NU) return; }

    const __half* __restrict__ src = is_user ? bh(cur) : uh(cur);
    __half* __restrict__ out       = is_user ? g_mh_u : g_mh_b;
    const int* __restrict__ offs   = is_user ? g_offs_u : g_offs_b;
    const int* __restrict__ idx    = is_user ? g_csr_u : g_csr_b;

    int s = offs[w], e = offs[w + 1];
    const int c4 = lane * 4;

    float ax = 0.f, ay = 0.f, az = 0.f, aw = 0.f;
    int j = s;
    for (; j + 4 <= e; j += 4) {
        int n0 = idx[j], n1 = idx[j + 1], n2 = idx[j + 2], n3 = idx[j + 3];
        uint2 r0 = *(const uint2*)(src + (size_t)n0 * HD + c4);
        uint2 r1 = *(const uint2*)(src + (size_t)n1 * HD + c4);
        uint2 r2 = *(const uint2*)(src + (size_t)n2 * HD + c4);
        uint2 r3 = *(const uint2*)(src + (size_t)n3 * HD + c4);
#pragma unroll
        for (int q = 0; q < 4; q++) {
            uint2 r = (q == 0) ? r0 : (q == 1) ? r1 : (q == 2) ? r2 : r3;
            float2 f0 = __half22float2(*(__half2*)&r.x);
            float2 f1 = __half22float2(*(__half2*)&r.y);
            ax += f0.x; ay += f0.y; az += f1.x; aw += f1.y;
        }
    }
    for (; j < e; j++) {
        uint2 r = *(const uint2*)(src + (size_t)idx[j] * HD + c4);
        float2 f0 = __half22float2(*(__half2*)&r.x);
        float2 f1 = __half22float2(*(__half2*)&r.y);
        ax += f0.x; ay += f0.y; az += f1.x; aw += f1.y;
    }
    float invd = 1.0f / fmaxf((float)(e - s), 1.0f);
    __half2 m01 = __float22half2_rn(make_float2(ax * invd, ay * invd));
    __half2 m23 = __float22half2_rn(make_float2(az * invd, aw * invd));
    uint2 o; o.x = *(uint32_t*)&m01; o.y = *(uint32_t*)&m23;
    *(uint2*)(out + (size_t)w * HD + c4) = o;
}

// ---------------- projection GEMM (SIMT, fp32 in, fp16 hi/lo out) -------------
__global__ void __launch_bounds__(256) proj_gemm(
        const float* __restrict__ A, int K,
        const float* __restrict__ W, const float* __restrict__ bias,
        int is_user) {
    __shared__ float As[16][64];
    __shared__ float Bs[16][128];

    __half* __restrict__ Ch = is_user ? g_uh0 : g_bh0;
    __half* __restrict__ Cl = is_user ? g_ul0 : g_bl0;
    const int N = is_user ? NU : NB;

    const int tid = threadIdx.x;
    const int tx = tid & 31;
    const int ty = tid >> 5;
    const int m_load = tid >> 2;
    const int k_load = (tid & 3) * 4;
    const int row0 = blockIdx.x * 64;
    const int row_l = row0 + m_load;

    float acc[8][4];
#pragma unroll
    for (int i = 0; i < 8; i++)
#pragma unroll
        for (int j = 0; j < 4; j++) acc[i][j] = 0.f;

    for (int kt = 0; kt < K; kt += 16) {
        float4 av = make_float4(0.f, 0.f, 0.f, 0.f);
        if (row_l < N)
            av = *(const float4*)(A + (size_t)row_l * K + kt + k_load);
        As[k_load + 0][m_load] = av.x;
        As[k_load + 1][m_load] = av.y;
        As[k_load + 2][m_load] = av.z;
        As[k_load + 3][m_load] = av.w;
        {
            int f = tid * 4;
            *(float4*)&Bs[f >> 7][f & 127] =
                *(const float4*)(W + (size_t)(kt + (f >> 7)) * 128 + (f & 127));
            int f2 = f + 1024;
            *(float4*)&Bs[f2 >> 7][f2 & 127] =
                *(const float4*)(W + (size_t)(kt + (f2 >> 7)) * 128 + (f2 & 127));
        }
        __syncthreads();
#pragma unroll
        for (int k = 0; k < 16; k++) {
            float4 b0 = *(float4*)&Bs[k][tx * 4];
            float a0[8];
            *(float4*)&a0[0] = *(float4*)&As[k][ty * 8];
            *(float4*)&a0[4] = *(float4*)&As[k][ty * 8 + 4];
#pragma unroll
            for (int i = 0; i < 8; i++) {
                acc[i][0] += a0[i] * b0.x;
                acc[i][1] += a0[i] * b0.y;
                acc[i][2] += a0[i] * b0.z;
                acc[i][3] += a0[i] * b0.w;
            }
        }
        __syncthreads();
    }

    float4 bb = *(const float4*)(bias + tx * 4);
#pragma unroll
    for (int i = 0; i < 8; i++) {
        int row = row0 + ty * 8 + i;
        if (row < N) {
            float ox = acc[i][0] + bb.x, oy = acc[i][1] + bb.y;
            float oz = acc[i][2] + bb.z, ow = acc[i][3] + bb.w;
            __half2 h01 = __float22half2_rn(make_float2(ox, oy));
            __half2 h23 = __float22half2_rn(make_float2(oz, ow));
            float2 f01 = __half22float2(h01);
            float2 f23 = __half22float2(h23);
            __half2 l01 = __float22half2_rn(make_float2(ox - f01.x, oy - f01.y));
            __half2 l23 = __float22half2_rn(make_float2(oz - f23.x, ow - f23.y));
            uint2 vh; vh.x = *(uint32_t*)&h01; vh.y = *(uint32_t*)&h23;
            uint2 vl; vl.x = *(uint32_t*)&l01; vl.y = *(uint32_t*)&l23;
            *(uint2*)(Ch + (size_t)row * 128 + tx * 4) = vh;
            *(uint2*)(Cl + (size_t)row * 128 + tx * 4) = vl;
        }
    }
}

// ---------------- tensor-core SAGE GEMM (both directions in one launch) --------
// out = relu([mean|X] @ [Wl;Wr] + bias)
// mean half (chunks 0-1): Ah@Bh (mean already fp16-lossy -> 1 product)
// X half    (chunks 2-3): Ah@Bh + Ah@Bl + Al@Bh (exact split, 3 products)
#define AST 72   // fp16 row stride in smem (conflict-free for fragment loads)
#define SMS_BIAS 0
#define SMS_AHI  1024
#define SMS_ALO  (SMS_AHI + 128 * AST * 2)
#define SMS_BHI  (SMS_ALO + 128 * AST * 2)
#define SMS_BLO  (SMS_BHI + 128 * AST * 2)
#define SMS_TOT  (SMS_BLO + 128 * AST * 2)

__device__ __forceinline__ void mma16816(float* d, const uint32_t* a,
                                         uint32_t b0, uint32_t b1) {
    asm volatile(
        "mma.sync.aligned.m16n8k16.row.col.f32.f16.f16.f32 "
        "{%0,%1,%2,%3}, {%4,%5,%6,%7}, {%8,%9}, {%0,%1,%2,%3};"
        : "+f"(d[0]), "+f"(d[1]), "+f"(d[2]), "+f"(d[3])
        : "r"(a[0]), "r"(a[1]), "r"(a[2]), "r"(a[3]), "r"(b0), "r"(b1));
}

__global__ void __launch_bounds__(256, 2) sage_mma(
        int cur,
        const float* __restrict__ Wl, const float* __restrict__ Wr,
        const float* __restrict__ bias) {
    extern __shared__ char smem[];
    const int tid = threadIdx.x;
    const int wid = tid >> 5;
    const int lane = tid & 31;

    int is_user, tile;
    if (blockIdx.x < TB) { is_user = 0; tile = blockIdx.x; }
    else                 { is_user = 1; tile = blockIdx.x - TB; }

    const __half* __restrict__ meanh = is_user ? g_mh_u : g_mh_b;
    const __half* __restrict__ Xh    = is_user ? uh(cur) : bh(cur);
    const __half* __restrict__ Xl    = is_user ? ul(cur) : bl(cur);
    __half* __restrict__ Oh          = is_user ? uh(cur ^ 1) : bh(cur ^ 1);
    __half* __restrict__ Ol          = is_user ? ul(cur ^ 1) : bl(cur ^ 1);
    const int N = is_user ? NU : NB;
    const int row0 = tile * 128;

    if (tid < 128) *(float*)(smem + SMS_BIAS + tid * 4) = bias[tid];

    const int warp_r = wid >> 1;
    const int warp_c = wid & 1;
    const int gid = lane >> 2;
    const int tig = lane & 3;

    float acc[2][8][4];
#pragma unroll
    for (int t = 0; t < 2; t++)
#pragma unroll
        for (int j = 0; j < 8; j++)
#pragma unroll
            for (int q = 0; q < 4; q++) acc[t][j][q] = 0.f;

    const int a_kq = (tid & 15) * 4;
    const int a_m0 = tid >> 4;
    const int bn = tid & 127;
    const int bk0 = (tid >> 7) * 32;

#pragma unroll 1
    for (int c = 0; c < 4; c++) {
        __syncthreads();

        const int kg0 = c * 64;
        const bool xpart = (kg0 >= 128);
        if (!xpart) {
            // mean chunk: fp16 hi already in global -> straight copy (no lo)
#pragma unroll
            for (int i = 0; i < 8; i++) {
                int m = a_m0 + i * 16;
                int gr = row0 + m;
                uint2 vh = make_uint2(0u, 0u);
                if (gr < N) vh = *(const uint2*)(meanh + (size_t)gr * 128 + kg0 + a_kq);
                uint32_t off = (uint32_t)(m * AST + a_kq) * 2;
                *(uint2*)(smem + SMS_AHI + off) = vh;
            }
        } else {
            // X chunk: hi/lo split in global -> straight copies
            const int akoff = kg0 - 128;
#pragma unroll
            for (int i = 0; i < 8; i++) {
                int m = a_m0 + i * 16;
                int gr = row0 + m;
                uint2 vh = make_uint2(0u, 0u), vl = make_uint2(0u, 0u);
                if (gr < N) {
                    vh = *(const uint2*)(Xh + (size_t)gr * 128 + akoff + a_kq);
                    vl = *(const uint2*)(Xl + (size_t)gr * 128 + akoff + a_kq);
                }
                uint32_t off = (uint32_t)(m * AST + a_kq) * 2;
                *(uint2*)(smem + SMS_AHI + off) = vh;
                *(uint2*)(smem + SMS_ALO + off) = vl;
            }
        }

        // ---- stage B chunk: Bs[n][k] = W[kb+k][n] (lo only for X chunks)
        const float* __restrict__ wsrc = xpart ? Wr : Wl;
        const int kb = xpart ? kg0 - 128 : kg0;
#pragma unroll 8
        for (int j = 0; j < 32; j++) {
            int kk = bk0 + j;
            float w = wsrc[(size_t)(kb + kk) * 128 + bn];
            __half h = __float2half_rn(w);
            uint32_t off = (uint32_t)(bn * AST + kk) * 2;
            *(__half*)(smem + SMS_BHI + off) = h;
            if (xpart) {
                __half l = __float2half_rn(w - __half2float(h));
                *(__half*)(smem + SMS_BLO + off) = l;
            }
        }
        __syncthreads();

        // ---- compute: 4 k16-steps
#pragma unroll
        for (int ks = 0; ks < 4; ks++) {
            const int k0 = ks * 16;
            uint32_t ahr[8], alr[8];
#pragma unroll
            for (int t = 0; t < 2; t++) {
                int r0 = warp_r * 32 + t * 16 + gid;
                uint32_t o0 = (uint32_t)(r0 * AST + k0 + tig * 2) * 2;
                uint32_t o1 = (uint32_t)((r0 + 8) * AST + k0 + tig * 2) * 2;
                ahr[t * 4 + 0] = *(const uint32_t*)(smem + SMS_AHI + o0);
                ahr[t * 4 + 1] = *(const uint32_t*)(smem + SMS_AHI + o1);
                ahr[t * 4 + 2] = *(const uint32_t*)(smem + SMS_AHI + o0 + 16);
                ahr[t * 4 + 3] = *(const uint32_t*)(smem + SMS_AHI + o1 + 16);
                if (xpart) {
                    alr[t * 4 + 0] = *(const uint32_t*)(smem + SMS_ALO + o0);
                    alr[t * 4 + 1] = *(const uint32_t*)(smem + SMS_ALO + o1);
                    alr[t * 4 + 2] = *(const uint32_t*)(smem + SMS_ALO + o0 + 16);
                    alr[t * 4 + 3] = *(const uint32_t*)(smem + SMS_ALO + o1 + 16);
                }
            }
#pragma unroll
            for (int j = 0; j < 8; j++) {
                int n = warp_c * 64 + j * 8 + gid;
                uint32_t ob = (uint32_t)(n * AST + k0 + tig * 2) * 2;
                uint32_t bh0 = *(const uint32_t*)(smem + SMS_BHI + ob);
                uint32_t bh1 = *(const uint32_t*)(smem + SMS_BHI + ob + 16);
                if (xpart) {
                    uint32_t bl0 = *(const uint32_t*)(smem + SMS_BLO + ob);
                    uint32_t bl1 = *(const uint32_t*)(smem + SMS_BLO + ob + 16);
#pragma unroll
                    for (int t = 0; t < 2; t++) {
                        mma16816(acc[t][j], ahr + t * 4, bh0, bh1);
                        mma16816(acc[t][j], ahr + t * 4, bl0, bl1);
                        mma16816(acc[t][j], alr + t * 4, bh0, bh1);
                    }
                } else {
#pragma unroll
                    for (int t = 0; t < 2; t++)
                        mma16816(acc[t][j], ahr + t * 4, bh0, bh1);
                }
            }
        }
    }

    // ---- epilogue: bias + relu, fp16 hi/lo stores
    const float* bias_s = (const float*)(smem + SMS_BIAS);
#pragma unroll
    for (int t = 0; t < 2; t++) {
        int r_lo = row0 + warp_r * 32 + t * 16 + gid;
        int r_hi = r_lo + 8;
#pragma unroll
        for (int j = 0; j < 8; j++) {
            int col = warp_c * 64 + j * 8 + tig * 2;
            float bx = bias_s[col], by = bias_s[col + 1];
            if (r_lo < N) {
                float ox = fmaxf(acc[t][j][0] + bx, 0.f);
                float oy = fmaxf(acc[t][j][1] + by, 0.f);
                __half2 h = __float22half2_rn(make_float2(ox, oy));
                float2 f = __half22float2(h);
                __half2 l = __float22half2_rn(make_float2(ox - f.x, oy - f.y));
                *(__half2*)(Oh + (size_t)r_lo * 128 + col) = h;
                *(__half2*)(Ol + (size_t)r_lo * 128 + col) = l;
            }
            if (r_hi < N) {
                float ox = fmaxf(acc[t][j][2] + bx, 0.f);
                float oy = fmaxf(acc[t][j][3] + by, 0.f);
                __half2 h = __float22half2_rn(make_float2(ox, oy));
                float2 f = __half22float2(h);
                __half2 l = __float22half2_rn(make_float2(ox - f.x, oy - f.y));
                *(__half2*)(Oh + (size_t)r_hi * 128 + col) = h;
                *(__half2*)(Ol + (size_t)r_hi * 128 + col) = l;
            }
        }
    }
}

// ---------------- layernorm (both populations, 1 warp / row) -------------------
__global__ void __launch_bounds__(256) ln_kernel(
        int cur,
        const float* __restrict__ ug, const float* __restrict__ ube,
        const float* __restrict__ bg, const float* __restrict__ bbe,
        float* __restrict__ out) {
    int gw   = (blockIdx.x * blockDim.x + threadIdx.x) >> 5;
    int lane = threadIdx.x & 31;
    if (gw >= NU + NB) return;

    int is_user = (gw < NU);
    int w = is_user ? gw : gw - NU;
    const __half* __restrict__ Xh = is_user ? uh(cur) : bh(cur);
    const __half* __restrict__ Xl = is_user ? ul(cur) : bl(cur);
    const float* gamma = is_user ? ug : bg;
    const float* beta  = is_user ? ube : bbe;
    float* op = out + (size_t)gw * 128;   // users first, then books

    uint2 vh = *(const uint2*)(Xh + (size_t)w * 128 + lane * 4);
    uint2 vl = *(const uint2*)(Xl + (size_t)w * 128 + lane * 4);
    float2 h0 = __half22float2(*(__half2*)&vh.x);
    float2 h1 = __half22float2(*(__half2*)&vh.y);
    float2 l0 = __half22float2(*(__half2*)&vl.x);
    float2 l1 = __half22float2(*(__half2*)&vl.y);
    float4 v;
    v.x = h0.x + l0.x; v.y = h0.y + l0.y;
    v.z = h1.x + l1.x; v.w = h1.y + l1.y;

    float s = v.x + v.y + v.z + v.w;
#pragma unroll
    for (int o = 16; o; o >>= 1) s += __shfl_xor_sync(0xffffffffu, s, o);
    float mean = s * (1.0f / 128.0f);

    float dx = v.x - mean, dy = v.y - mean, dz = v.z - mean, dw = v.w - mean;
    float q = dx * dx + dy * dy + dz * dz + dw * dw;
#pragma unroll
    for (int o = 16; o; o >>= 1) q += __shfl_xor_sync(0xffffffffu, q, o);
    float rs = rsqrtf(q * (1.0f / 128.0f) + 1e-5f);

    float4 g  = *(const float4*)(gamma + lane * 4);
    float4 bt = *(const float4*)(beta + lane * 4);
    float4 o4;
    o4.x = dx * rs * g.x + bt.x;
    o4.y = dy * rs * g.y + bt.y;
    o4.z = dz * rs * g.z + bt.z;
    o4.w = dw * rs * g.w + bt.w;
    *(float4*)(op + lane * 4) = o4;
}

// ---------------- launch --------------------------------------------------------
extern "C" void kernel_launch(void* const* d_in, const int* in_sizes, int n_in,
                              void* d_out, int out_size) {
    const float* user_x = (const float*)d_in[0];
    const float* book_x = (const float*)d_in[1];
    const int*   esrc   = (const int*)d_in[2];
    const int*   edst   = (const int*)d_in[3];
    const float* upw    = (const float*)d_in[4];
    const float* upb    = (const float*)d_in[5];
    const float* bpw    = (const float*)d_in[6];
    const float* bpb    = (const float*)d_in[7];
    const float* Wl     = (const float*)d_in[8];
    const float* bl_    = (const float*)d_in[9];
    const float* Wr     = (const float*)d_in[10];
    const float* ug     = (const float*)d_in[11];
    const float* ube    = (const float*)d_in[12];
    const float* bg     = (const float*)d_in[13];
    const float* bbe    = (const float*)d_in[14];
    float* out = (float*)d_out;

    (void)in_sizes; (void)n_in; (void)out_size;

    cudaFuncSetAttribute(sage_mma, cudaFuncAttributeMaxDynamicSharedMemorySize, SMS_TOT);

    int* d_offs_u; cudaGetSymbolAddress((void**)&d_offs_u, g_offs_u);
    int* d_offs_b; cudaGetSymbolAddress((void**)&d_offs_b, g_offs_b);
    int* d_deg_u;  cudaGetSymbolAddress((void**)&d_deg_u,  g_deg_u);
    int* d_deg_b;  cudaGetSymbolAddress((void**)&d_deg_b,  g_deg_b);
    int* d_bsum_u; cudaGetSymbolAddress((void**)&d_bsum_u, g_bsum_u);
    int* d_bsum_b; cudaGetSymbolAddress((void**)&d_bsum_b, g_bsum_b);

    // ---- CSR build (once; reused by all 3 layers) ----
    zero_deg_kernel<<<(NU + NB + 255) / 256, 256>>>();
    deg_kernel<<<(NE + 255) / 256, 256>>>(esrc, edst);
    scan_blocks<<<NBLK_U, 1024>>>(d_deg_u, d_offs_u, d_bsum_u, NU);
    scan_blocks<<<NBLK_B, 1024>>>(d_deg_b, d_offs_b, d_bsum_b, NB);
    scan_small<<<1, 256>>>(d_bsum_u, NBLK_U);
    scan_small<<<1, 256>>>(d_bsum_b, NBLK_B);
    scan_add<<<(NU + 255) / 256, 256>>>(d_offs_u, d_bsum_u, NU, NBLK_U);
    scan_add<<<(NB + 255) / 256, 256>>>(d_offs_b, d_bsum_b, NB, NBLK_B);
    copy_cursor_kernel<<<(NU + NB + 255) / 256, 256>>>();
    fill_kernel<<<(NE + 255) / 256, 256>>>(esrc, edst);

    // ---- projections ----
    proj_gemm<<<(NU + 63) / 64, 256>>>(user_x, DU, upw, upb, 1);
    proj_gemm<<<(NB + 63) / 64, 256>>>(book_x, DB, bpw, bpb, 0);

    int cur = 0;
    const int gblocks = (int)(((size_t)(NU + NB) * 32 + 255) / 256);
    for (int l = 0; l < 3; l++) {
        gather_mean<<<gblocks, 256>>>(cur);
        sage_mma<<<TB + TU, 256, SMS_TOT>>>(cur, Wl + (size_t)l * 128 * 128,
                                            Wr + (size_t)l * 128 * 128,
                                            bl_ + (size_t)l * 128);
        cur ^= 1;
    }

    ln_kernel<<<(int)(((size_t)(NU + NB) * 32 + 255) / 256), 256>>>(
        cur, ug, ube, bg, bbe, out);
}